// round 13
// baseline (speedup 1.0000x reference)
#include <cuda_runtime.h>
#include <cuda_bf16.h>
#include <cuda_fp16.h>
#include <math.h>
#include <stdint.h>

// ---------------- problem constants ----------------
#define BB   16
#define TT   4096
#define NR   (BB*TT)
#define TSD  64
#define DE   128
#define HH   256
#define LDF  512
#define LDH  256
#define OD   10
#define NBLKS 6
#define EPSV 1e-5f
#define NCH  16
#define CLEN 256

// ---------------- scratch ----------------
static __device__ __align__(256) float  g_yenc[(size_t)NR*DE];  // fp32 residual anchor
static __device__ __align__(256) __half g_h  [(size_t)NR*DE];   // running hidden, fp16
static __device__ __align__(256) __half g_bu [(size_t)NR*512];  // Bu -> state (in place), fp16
static __device__ float2 g_lam [NBLKS*HH];
static __device__ float  g_gamma[NBLKS*HH];
static __device__ float  g_bnpart[512*2*DE];
static __device__ float  g_bna[DE];
static __device__ float  g_bnb[DE];
static __device__ float  g_bubias[512];
static __device__ float2 g_carry[BB*NCH*HH];
static __device__ float2 g_inc  [BB*NCH*HH];

// weights
static __device__ __align__(256) float  g_WBf[(size_t)NBLKS*512*128]; // gamma-scaled fp32 master
static __device__ __align__(256) __half g_WBfh[512*128];              // per-block BN-folded, fp16 split
static __device__ __align__(256) __half g_WBfl[512*128];
static __device__ __align__(256) __nv_bfloat16 g_WEh[128*64];
static __device__ __align__(256) __nv_bfloat16 g_WEl[128*64];
static __device__ __align__(256) __half g_WCh[(size_t)NBLKS*128*512];
static __device__ __align__(256) __half g_WCl[(size_t)NBLKS*128*512];
static __device__ __align__(256) __half g_W1h[(size_t)NBLKS*512*128];
static __device__ __align__(256) __half g_W1l[(size_t)NBLKS*512*128];
static __device__ __align__(256) __half g_W2h[(size_t)NBLKS*128*256];
static __device__ __align__(256) __half g_W2l[(size_t)NBLKS*128*256];

// ---------------- helpers ----------------
__device__ __forceinline__ uint32_t smem_u32(const void* p) {
    uint32_t a;
    asm("{ .reg .u64 t; cvta.to.shared.u64 t, %1; cvt.u32.u64 %0, t; }" : "=r"(a) : "l"(p));
    return a;
}
__device__ __forceinline__ void cp16(uint32_t dst, const void* src) {
    asm volatile("cp.async.cg.shared.global [%0], [%1], 16;" :: "r"(dst), "l"(src));
}
#define CP_COMMIT() asm volatile("cp.async.commit_group;" ::: "memory")
#define CP_WAIT0()  asm volatile("cp.async.wait_group 0;" ::: "memory")

#define MMA_BF16(d, a, b0, b1) \
    asm volatile("mma.sync.aligned.m16n8k16.row.col.f32.bf16.bf16.f32 " \
        "{%0,%1,%2,%3}, {%4,%5,%6,%7}, {%8,%9}, {%0,%1,%2,%3};" \
        : "+f"((d)[0]), "+f"((d)[1]), "+f"((d)[2]), "+f"((d)[3]) \
        : "r"((a)[0]), "r"((a)[1]), "r"((a)[2]), "r"((a)[3]), "r"(b0), "r"(b1))

#define MMA_F16(d, a, b0, b1) \
    asm volatile("mma.sync.aligned.m16n8k16.row.col.f32.f16.f16.f32 " \
        "{%0,%1,%2,%3}, {%4,%5,%6,%7}, {%8,%9}, {%0,%1,%2,%3};" \
        : "+f"((d)[0]), "+f"((d)[1]), "+f"((d)[2]), "+f"((d)[3]) \
        : "r"((a)[0]), "r"((a)[1]), "r"((a)[2]), "r"((a)[3]), "r"(b0), "r"(b1))

#define LDSM4(r, addr) \
    asm volatile("ldmatrix.sync.aligned.m8n8.x4.shared.b16 {%0,%1,%2,%3}, [%4];" \
        : "=r"((r)[0]), "=r"((r)[1]), "=r"((r)[2]), "=r"((r)[3]) : "r"(addr))

__device__ __forceinline__ void split_store(float v, __nv_bfloat16* hi, __nv_bfloat16* lo, size_t i) {
    __nv_bfloat16 h = __float2bfloat16(v);
    hi[i] = h;
    lo[i] = __float2bfloat16(v - __bfloat162float(h));
}
__device__ __forceinline__ void split_store_h(float v, __half* hi, __half* lo, size_t i) {
    __half h = __float2half_rn(v);
    hi[i] = h;
    lo[i] = __float2half_rn(v - __half2float(h));
}

// ---------------- prep ----------------
__global__ void prep_lam_kernel(const float* __restrict__ nu_log,
                                const float* __restrict__ theta_log) {
    int blk = blockIdx.x;
    int h   = threadIdx.x;
    float nu = nu_log[blk*HH + h];
    float th = theta_log[blk*HH + h];
    float r  = expf(-expf(nu));
    float ang = expf(th);
    float sn, cs;
    sincosf(ang, &sn, &cs);
    float2 lam; lam.x = r*cs; lam.y = r*sn;
    g_lam[blk*HH + h]   = lam;
    g_gamma[blk*HH + h] = sqrtf(fmaxf(1.f - r*r, 1e-8f));
}
__global__ void prep_WBf_kernel(const float* __restrict__ Bre, const float* __restrict__ Bim) {
    int idx = blockIdx.x*256 + threadIdx.x;
    if (idx >= NBLKS*512*DE) return;
    int k = idx & 127;
    int n = (idx >> 7) & 511;
    int blk = idx >> 16;
    int h = n >> 1;
    float g = g_gamma[blk*HH + h];
    g_WBf[idx] = ((n & 1) ? Bim : Bre)[((size_t)blk*HH + h)*DE + k] * g;
}
__global__ void prep_WC_kernel(const float* __restrict__ Cre, const float* __restrict__ Cim) {
    int idx = blockIdx.x*256 + threadIdx.x;
    if (idx >= NBLKS*DE*512) return;
    int k = idx & 511;
    int n = (idx >> 9) & 127;
    int blk = idx >> 16;
    int h = k >> 1;
    float v = (k & 1) ? -Cim[((size_t)blk*DE + n)*HH + h] : Cre[((size_t)blk*DE + n)*HH + h];
    split_store_h(v, g_WCh, g_WCl, idx);
}
__global__ void prep_W1_kernel(const float* __restrict__ W1) {
    int idx = blockIdx.x*256 + threadIdx.x;
    if (idx >= NBLKS*512*DE) return;
    int k = idx & 127;
    int n = (idx >> 7) & 511;
    int blk = idx >> 16;
    split_store_h(W1[((size_t)blk*DE + k)*LDF + n], g_W1h, g_W1l, idx);
}
__global__ void prep_W2_kernel(const float* __restrict__ W2) {
    int idx = blockIdx.x*256 + threadIdx.x;
    if (idx >= NBLKS*DE*256) return;
    int k = idx & 255;
    int n = (idx >> 8) & 127;
    int blk = idx >> 15;
    split_store_h(W2[((size_t)blk*LDH + k)*DE + n], g_W2h, g_W2l, idx);
}
__global__ void prep_WE_kernel(const float* __restrict__ We) {
    int idx = blockIdx.x*256 + threadIdx.x;
    if (idx >= DE*TSD) return;
    int k = idx & 63;
    int n = idx >> 6;
    split_store(We[(size_t)k*DE + n], g_WEh, g_WEl, idx);
}

// ---------------- batchnorm stage-2 + BN fold into Bu weights ----------------
__global__ void bn_stats2_kernel(const float* __restrict__ scale,
                                 const float* __restrict__ bias) {
    __shared__ float ss[512], sq[512];
    int tid = threadIdx.x;
    int f = tid & 127;
    int grp = tid >> 7;
    float s = 0.f, s2 = 0.f;
    for (int i = grp; i < 512; i += 4) {
        s  += g_bnpart[i*(2*DE) + f];
        s2 += g_bnpart[i*(2*DE) + DE + f];
    }
    ss[tid] = s;
    sq[tid] = s2;
    __syncthreads();
    if (tid < 128) {
        s  = ss[tid] + ss[128+tid] + ss[256+tid] + ss[384+tid];
        s2 = sq[tid] + sq[128+tid] + sq[256+tid] + sq[384+tid];
        float mean = s * (1.f/NR);
        float var  = s2 * (1.f/NR) - mean*mean;
        float a = scale[tid] * rsqrtf(var + EPSV);
        g_bna[tid] = a;
        g_bnb[tid] = fmaf(-mean, a, bias[tid]);
    }
}
__global__ void fold_WB_kernel(int blk) {
    int idx = blockIdx.x*256 + threadIdx.x;
    int k = idx & 127;
    float v = g_WBf[(size_t)blk*512*128 + idx] * g_bna[k];
    split_store_h(v, g_WBfh, g_WBfl, idx);
}
__global__ void fold_bias_kernel(int blk) {
    int n = threadIdx.x;
    const float* w = g_WBf + (size_t)blk*512*128 + (size_t)n*128;
    float s = 0.f;
    #pragma unroll 4
    for (int k = 0; k < 128; k++) s = fmaf(g_bnb[k], w[k], s);
    g_bubias[n] = s;
}

#define PITCH 72
#define UNITE (128*PITCH)
#define NTHR 512

// ---------------- standalone GEMM (encoder, Bu) ----------------
template<int KDIM, int OUTW, int MODE_A, int EPI, int AF16, int OUTH, int STATS, int NBT>
__global__ void __launch_bounds__(NTHR) gemm_mma(
    const void* __restrict__ Av,
    const void* __restrict__ Bhi_, const void* __restrict__ Blo_,
    void* __restrict__ Cv,
    const float* __restrict__ bias)
{
    constexpr int ABUFS = AF16 ? 1 : 2;
    constexpr int BROWS = 32 * NBT;
    constexpr int BUNIT = BROWS * PITCH;
    constexpr int O_AH = 0, O_AL = UNITE;
    constexpr int O_BH = ABUFS*UNITE;
    constexpr int O_BL = O_BH + BUNIT;
    constexpr int STAGE = ABUFS*UNITE + 2*BUNIT;
    constexpr int NCHK = KDIM / 64;
    constexpr int CPB_IT = (BROWS*16)/NTHR;

    extern __shared__ __nv_bfloat16 sm[];
    const uint32_t smb = smem_u32(sm);
    const int tid  = threadIdx.x;
    const int lane = tid & 31;
    const int wid  = tid >> 5;
    const int wr   = wid & 3;
    const int wc4  = wid >> 2;
    const int g    = lane >> 2;
    const int t    = lane & 3;
    const int bm   = blockIdx.y << 7;
    const int bn   = blockIdx.x * (32*NBT);

    const int aLaneE = (lane & 15)*PITCH + (lane >> 4)*8;
    const int bLaneE = (lane & 7)*PITCH + ((lane >> 4) & 1)*(8*PITCH) + ((lane >> 3) & 1)*8;

    float accg[2][NBT][4];
    #pragma unroll
    for (int rb = 0; rb < 2; rb++)
        #pragma unroll
        for (int nb = 0; nb < NBT; nb++)
            #pragma unroll
            for (int j = 0; j < 4; j++) accg[rb][nb][j] = 0.f;

    float4 areg[4];
    auto loadA = [&](int cc) {
        const float* Af = (const float*)Av;
        #pragma unroll
        for (int i = 0; i < 4; i++) {
            int idx = tid + NTHR*i;
            int row = idx >> 4;
            int col4 = (idx & 15) << 2;
            areg[i] = *(const float4*)(Af + (size_t)(bm + row)*KDIM + cc*64 + col4);
        }
    };
    auto storeA = [&](int cc, int so) {
        #pragma unroll
        for (int i = 0; i < 4; i++) {
            int idx = tid + NTHR*i;
            int row = idx >> 4;
            int col4 = (idx & 15) << 2;
            float4 v = areg[i];
            __nv_bfloat16 h0 = __float2bfloat16(v.x), h1 = __float2bfloat16(v.y);
            __nv_bfloat16 h2 = __float2bfloat16(v.z), h3 = __float2bfloat16(v.w);
            __nv_bfloat16 l0 = __float2bfloat16(v.x - __bfloat162float(h0));
            __nv_bfloat16 l1 = __float2bfloat16(v.y - __bfloat162float(h1));
            __nv_bfloat16 l2 = __float2bfloat16(v.z - __bfloat162float(h2));
            __nv_bfloat16 l3 = __float2bfloat16(v.w - __bfloat162float(h3));
            uint32_t hu0 = ((uint32_t)__bfloat16_as_ushort(h1) << 16) | __bfloat16_as_ushort(h0);
            uint32_t hu1 = ((uint32_t)__bfloat16_as_ushort(h3) << 16) | __bfloat16_as_ushort(h2);
            uint32_t lu0 = ((uint32_t)__bfloat16_as_ushort(l1) << 16) | __bfloat16_as_ushort(l0);
            uint32_t lu1 = ((uint32_t)__bfloat16_as_ushort(l3) << 16) | __bfloat16_as_ushort(l2);
            int off = row*PITCH + col4;
            *(uint2*)(sm + so + O_AH + off) = make_uint2(hu0, hu1);
            *(uint2*)(sm + so + O_AL + off) = make_uint2(lu0, lu1);
        }
    };
    auto cpA16 = [&](int cc, int so) {
        const __half* Ahalf = (const __half*)Av;
        #pragma unroll
        for (int i = 0; i < 2; i++) {
            int idx = tid + NTHR*i;
            int r = idx >> 3;
            int q = idx & 7;
            cp16(smb + (uint32_t)((so + O_AH + r*PITCH + q*8)*2),
                 Ahalf + (size_t)(bm + r)*KDIM + cc*64 + q*8);
        }
    };
    auto cpB = [&](int cc, int so) {
        const __nv_bfloat16* Bh = (const __nv_bfloat16*)Bhi_;
        const __nv_bfloat16* Bl = (const __nv_bfloat16*)Blo_;
        #pragma unroll
        for (int i = 0; i < CPB_IT; i++) {
            int idx = tid + NTHR*i;
            int pl  = idx / (BROWS*8);
            int rem = idx % (BROWS*8);
            int r   = rem >> 3;
            int q   = rem & 7;
            const __nv_bfloat16* src = pl ? Bl : Bh;
            cp16(smb + (uint32_t)((so + (pl ? O_BL : O_BH) + r*PITCH + q*8)*2),
                 src + (size_t)(bn + r)*KDIM + cc*64 + q*8);
        }
    };

    if (AF16) cpA16(0, 0); else loadA(0);
    cpB(0, 0);
    CP_COMMIT();
    if (!AF16) {
        storeA(0, 0);
        if (NCHK > 1) loadA(1);
    }

    #pragma unroll 1
    for (int c = 0; c < NCHK; c++) {
        const int so = (c & 1)*STAGE;
        CP_WAIT0();
        __syncthreads();
        if (c + 1 < NCHK) {
            const int nso = ((c+1) & 1)*STAGE;
            cpB(c+1, nso);
            if (AF16) cpA16(c+1, nso);
            CP_COMMIT();
            if (!AF16) {
                storeA(c+1, nso);
                if (c + 2 < NCHK) loadA(c+2);
            }
        }
        #pragma unroll
        for (int kk = 0; kk < 4; kk++) {
            const int kkE = kk*16;
            uint32_t ah[2][4], al[2][4];
            #pragma unroll
            for (int rb = 0; rb < 2; rb++) {
                int abase = so + (32*wr + 16*rb)*PITCH + kkE + aLaneE;
                LDSM4(ah[rb], smb + (uint32_t)((O_AH + abase)*2));
                if (!AF16) LDSM4(al[rb], smb + (uint32_t)((O_AL + abase)*2));
            }
            #pragma unroll
            for (int nb2 = 0; nb2 < NBT/2; nb2++) {
                uint32_t bh[4], bl[4];
                int bbase = so + (8*NBT*wc4 + 16*nb2)*PITCH + kkE + bLaneE;
                LDSM4(bh, smb + (uint32_t)((O_BH + bbase)*2));
                LDSM4(bl, smb + (uint32_t)((O_BL + bbase)*2));
                #pragma unroll
                for (int rb = 0; rb < 2; rb++)
                    #pragma unroll
                    for (int j = 0; j < 2; j++) {
                        float* d = accg[rb][2*nb2 + j];
                        if (AF16) {
                            MMA_F16(d, ah[rb], bh[2*j], bh[2*j+1]);
                            MMA_F16(d, ah[rb], bl[2*j], bl[2*j+1]);
                        } else {
                            MMA_BF16(d, ah[rb], bh[2*j], bh[2*j+1]);
                            MMA_BF16(d, al[rb], bh[2*j], bh[2*j+1]);
                            MMA_BF16(d, ah[rb], bl[2*j], bl[2*j+1]);
                        }
                    }
            }
        }
    }

    float cs0[STATS ? NBT : 1], cs1[STATS ? NBT : 1], cq0[STATS ? NBT : 1], cq1[STATS ? NBT : 1];
    if (STATS) {
        #pragma unroll
        for (int nb = 0; nb < NBT; nb++) { cs0[nb]=0.f; cs1[nb]=0.f; cq0[nb]=0.f; cq1[nb]=0.f; }
    }
    #pragma unroll
    for (int rb = 0; rb < 2; rb++) {
        int m0 = bm + 32*wr + 16*rb + g;
        #pragma unroll
        for (int nb = 0; nb < NBT; nb++) {
            int col = bn + 8*NBT*wc4 + 8*nb + 2*t;
            float2 v0 = make_float2(accg[rb][nb][0], accg[rb][nb][1]);
            float2 v1 = make_float2(accg[rb][nb][2], accg[rb][nb][3]);
            if (bias != nullptr) {
                float2 bv = *(const float2*)(bias + col);
                v0.x += bv.x; v0.y += bv.y; v1.x += bv.x; v1.y += bv.y;
            }
            if (STATS) {
                cs0[nb] += v0.x + v1.x;
                cs1[nb] += v0.y + v1.y;
                cq0[nb] += v0.x*v0.x + v1.x*v1.x;
                cq1[nb] += v0.y*v0.y + v1.y*v1.y;
            }
            if (OUTH == 1) {
                __half* Ch = (__half*)Cv;
                *(__half2*)(Ch + (size_t)m0*OUTW + col)     = __floats2half2_rn(v0.x, v0.y);
                *(__half2*)(Ch + (size_t)(m0+8)*OUTW + col) = __floats2half2_rn(v1.x, v1.y);
            } else if (OUTH == 2) {
                float* Cf = (float*)Cv;
                *(float2*)(Cf + (size_t)m0*OUTW + col)     = v0;
                *(float2*)(Cf + (size_t)(m0+8)*OUTW + col) = v1;
                *(__half2*)(g_h + (size_t)m0*OUTW + col)     = __floats2half2_rn(v0.x, v0.y);
                *(__half2*)(g_h + (size_t)(m0+8)*OUTW + col) = __floats2half2_rn(v1.x, v1.y);
            } else {
                float* Cf = (float*)Cv;
                *(float2*)(Cf + (size_t)m0*OUTW + col)     = v0;
                *(float2*)(Cf + (size_t)(m0+8)*OUTW + col) = v1;
            }
        }
    }

    if (STATS) {
        #pragma unroll
        for (int nb = 0; nb < NBT; nb++) {
            #pragma unroll
            for (int m = 4; m <= 16; m <<= 1) {
                cs0[nb] += __shfl_xor_sync(0xffffffffu, cs0[nb], m);
                cs1[nb] += __shfl_xor_sync(0xffffffffu, cs1[nb], m);
                cq0[nb] += __shfl_xor_sync(0xffffffffu, cq0[nb], m);
                cq1[nb] += __shfl_xor_sync(0xffffffffu, cq1[nb], m);
            }
        }
        __syncthreads();
        float* spart = (float*)sm;
        if (lane < 4) {
            #pragma unroll
            for (int nb = 0; nb < NBT; nb++) {
                int col = 8*NBT*wc4 + 8*nb + 2*lane;
                spart[wr*128 + col]           = cs0[nb];
                spart[wr*128 + col + 1]       = cs1[nb];
                spart[512 + wr*128 + col]     = cq0[nb];
                spart[512 + wr*128 + col + 1] = cq1[nb];
            }
        }
        __syncthreads();
        if (tid < 128) {
            float s  = spart[tid] + spart[128+tid] + spart[256+tid] + spart[384+tid];
            float s2 = spart[512+tid] + spart[640+tid] + spart[768+tid] + spart[896+tid];
            g_bnpart[blockIdx.y*(2*DE) + tid]      = s;
            g_bnpart[blockIdx.y*(2*DE) + DE + tid] = s2;
        }
    }
}

// ---------------- fused cproj + GLU + W2 ----------------
// grid (1, 512): each CTA owns 128 rows. lru and glu live entirely in smem.
// smem (half units): stage1 pipeline [0,6*UNITE); then LRU [0,2*UNITE),
// B2 [2*UNITE,6*UNITE), GLU [6*UNITE,10*UNITE), B3 [0,2*UNITE).
#define S_LRU 0
#define S_BH2 (2*UNITE)
#define S_BL2 (4*UNITE)
#define S_GLU (6*UNITE)
#define S_BH3 0
#define S_BL3 UNITE
#define SMEM_FUSED (10*UNITE*2)   // 184320 bytes

__global__ void __launch_bounds__(NTHR) mlp_fused(
    const __half* __restrict__ state,
    const __half* __restrict__ WCh, const __half* __restrict__ WCl,
    const __half* __restrict__ W1hp, const __half* __restrict__ W1lp,
    const __half* __restrict__ W2hp, const __half* __restrict__ W2lp,
    __half* __restrict__ hout,
    const float* __restrict__ yenc,
    const float* __restrict__ b1,
    const float* __restrict__ b2,
    const float* __restrict__ dvec)
{
    extern __shared__ __half smh[];
    const uint32_t smb = smem_u32(smh);
    const int tid  = threadIdx.x;
    const int lane = tid & 31;
    const int wid  = tid >> 5;
    const int wr   = wid & 3;
    const int wc4  = wid >> 2;
    const int g    = lane >> 2;
    const int t    = lane & 3;
    const int bm   = blockIdx.y << 7;
    const int aLaneE = (lane & 15)*PITCH + (lane >> 4)*8;
    const int bLaneE = (lane & 7)*PITCH + ((lane >> 4) & 1)*(8*PITCH) + ((lane >> 3) & 1)*8;

    // ===== stage 1: lru = Re(state @ C) + BN(h)*D -> smem =====
    {
        const int O_AH = 0, O_BH = UNITE, O_BL = 2*UNITE, STG = 3*UNITE;
        float acc[2][4][4];
        #pragma unroll
        for (int rb = 0; rb < 2; rb++)
            #pragma unroll
            for (int nb = 0; nb < 4; nb++)
                #pragma unroll
                for (int j = 0; j < 4; j++) acc[rb][nb][j] = 0.f;

        auto cpA = [&](int cc, int so) {
            #pragma unroll
            for (int i = 0; i < 2; i++) {
                int idx = tid + NTHR*i;
                int r = idx >> 3;
                int q = idx & 7;
                cp16(smb + (uint32_t)((so + O_AH + r*PITCH + q*8)*2),
                     state + (size_t)(bm + r)*512 + cc*64 + q*8);
            }
        };
        auto cpBst = [&](int cc, int so) {
            #pragma unroll
            for (int i = 0; i < 4; i++) {
                int idx = tid + NTHR*i;
                int pl  = idx >> 10;
                int rem = idx & 1023;
                int r   = rem >> 3;
                int q   = rem & 7;
                const __half* src = pl ? WCl : WCh;
                cp16(smb + (uint32_t)((so + (pl ? O_BL : O_BH) + r*PITCH + q*8)*2),
                     src + (size_t)r*512 + cc*64 + q*8);
            }
        };

        cpA(0, 0);
        cpBst(0, 0);
        CP_COMMIT();
        #pragma unroll 1
        for (int c = 0; c < 8; c++) {
            const int so = (c & 1)*STG;
            CP_WAIT0();
            __syncthreads();
            if (c + 1 < 8) {
                const int nso = ((c+1) & 1)*STG;
                cpBst(c+1, nso);
                cpA(c+1, nso);
                CP_COMMIT();
            }
            #pragma unroll
            for (int kk = 0; kk < 4; kk++) {
                const int kkE = kk*16;
                uint32_t ah[2][4];
                #pragma unroll
                for (int rb = 0; rb < 2; rb++) {
                    int abase = so + (32*wr + 16*rb)*PITCH + kkE + aLaneE;
                    LDSM4(ah[rb], smb + (uint32_t)((O_AH + abase)*2));
                }
                #pragma unroll
                for (int nb2 = 0; nb2 < 2; nb2++) {
                    uint32_t bh[4], bl[4];
                    int bbase = so + (32*wc4 + 16*nb2)*PITCH + kkE + bLaneE;
                    LDSM4(bh, smb + (uint32_t)((O_BH + bbase)*2));
                    LDSM4(bl, smb + (uint32_t)((O_BL + bbase)*2));
                    #pragma unroll
                    for (int rb = 0; rb < 2; rb++)
                        #pragma unroll
                        for (int j = 0; j < 2; j++) {
                            float* d = acc[rb][2*nb2 + j];
                            MMA_F16(d, ah[rb], bh[2*j], bh[2*j+1]);
                            MMA_F16(d, ah[rb], bl[2*j], bl[2*j+1]);
                        }
                }
            }
        }
        // epilogue -> lru smem (writes [0,2*UNITE); last chunk read [3*UNITE,6*UNITE) — disjoint)
        #pragma unroll
        for (int rb = 0; rb < 2; rb++) {
            int m0l = 32*wr + 16*rb + g;
            #pragma unroll
            for (int nb = 0; nb < 4; nb++) {
                int col = 32*wc4 + 8*nb + 2*t;
                float2 aa = *(const float2*)(g_bna + col);
                float2 ab = *(const float2*)(g_bnb + col);
                float2 dv = *(const float2*)(dvec + col);
                float2 h0 = __half22float2(*(const __half2*)(hout + (size_t)(bm+m0l)*DE + col));
                float2 h1 = __half22float2(*(const __half2*)(hout + (size_t)(bm+m0l+8)*DE + col));
                float2 v0, v1;
                v0.x = acc[rb][nb][0] + fmaf(aa.x, h0.x, ab.x)*dv.x;
                v0.y = acc[rb][nb][1] + fmaf(aa.y, h0.y, ab.y)*dv.y;
                v1.x = acc[rb][nb][2] + fmaf(aa.x, h1.x, ab.x)*dv.x;
                v1.y = acc[rb][nb][3] + fmaf(aa.y, h1.y, ab.y)*dv.y;
                int base = S_LRU + (col >> 6)*UNITE + (col & 63);
                *(__half2*)(smh + base + m0l*PITCH)     = __floats2half2_rn(v0.x, v0.y);
                *(__half2*)(smh + base + (m0l+8)*PITCH) = __floats2half2_rn(v1.x, v1.y);
            }
        }
    }
    __syncthreads();

    // ===== stage 2: glu = GLU(lru @ W1 + b1) -> smem (two passes) =====
    #pragma unroll 1
    for (int pass = 0; pass < 2; pass++) {
        float ag[2][4][4], as_[2][4][4];
        #pragma unroll
        for (int rb = 0; rb < 2; rb++)
            #pragma unroll
            for (int nb = 0; nb < 4; nb++)
                #pragma unroll
                for (int j = 0; j < 4; j++) { ag[rb][nb][j] = 0.f; as_[rb][nb][j] = 0.f; }

        #pragma unroll 1
        for (int kc = 0; kc < 2; kc++) {
            __syncthreads();
            #pragma unroll
            for (int i = 0; i < 8; i++) {
                int idx = tid + NTHR*i;            // 4096
                int pl  = idx >> 11;
                int rem = idx & 2047;
                int r   = rem >> 3;                // 0..255
                int q   = rem & 7;
                int rowg = (r < 128) ? (128*pass + r) : (128 + 128*pass + r);
                const __half* src = pl ? W1lp : W1hp;
                cp16(smb + (uint32_t)(((pl ? S_BL2 : S_BH2) + r*PITCH + q*8)*2),
                     src + (size_t)rowg*128 + kc*64 + q*8);
            }
            CP_COMMIT();
            CP_WAIT0();
            __syncthreads();
            #pragma unroll
            for (int kk = 0; kk < 4; kk++) {
                const int kkE = kk*16;
                uint32_t ah[2][4];
                #pragma unroll
                for (int rb = 0; rb < 2; rb++) {
                    int abase = S_LRU + kc*UNITE + (32*wr + 16*rb)*PITCH + kkE + aLaneE;
                    LDSM4(ah[rb], smb + (uint32_t)(abase*2));
                }
                #pragma unroll
                for (int nb2 = 0; nb2 < 2; nb2++) {
                    uint32_t gh[4], gl[4], sh[4], sl[4];
                    int bo = (32*wc4 + 16*nb2)*PITCH + kkE + bLaneE;
                    LDSM4(gh, smb + (uint32_t)((S_BH2 + bo)*2));
                    LDSM4(gl, smb + (uint32_t)((S_BL2 + bo)*2));
                    LDSM4(sh, smb + (uint32_t)((S_BH2 + 128*PITCH + bo)*2));
                    LDSM4(sl, smb + (uint32_t)((S_BL2 + 128*PITCH + bo)*2));
                    #pragma unroll
                    for (int rb = 0; rb < 2; rb++)
                        #pragma unroll
                        for (int j = 0; j < 2; j++) {
                            float* dg = ag[rb][2*nb2 + j];
                            float* ds = as_[rb][2*nb2 + j];
                            MMA_F16(dg, ah[rb], gh[2*j], gh[2*j+1]);
                            MMA_F16(dg, ah[rb], gl[2*j], gl[2*j+1]);
                            MMA_F16(ds, ah[rb], sh[2*j], sh[2*j+1]);
                            MMA_F16(ds, ah[rb], sl[2*j], sl[2*j+1]);
                        }
                }
            }
        }
        // GLU epilogue -> glu smem (region disjoint from lru/B2)
        #pragma unroll
        for (int rb = 0; rb < 2; rb++) {
            int m0l = 32*wr + 16*rb + g;
            #pragma unroll
            for (int nb = 0; nb < 4; nb++) {
                int jl = 32*wc4 + 8*nb + 2*t;
                int jg = 128*pass + jl;
                float2 bg = *(const float2*)(b1 + jg);
                float2 bs = *(const float2*)(b1 + 256 + jg);
                float g0 = ag[rb][nb][0] + bg.x, s0 = as_[rb][nb][0] + bs.x;
                float g1 = ag[rb][nb][1] + bg.y, s1 = as_[rb][nb][1] + bs.y;
                float g2 = ag[rb][nb][2] + bg.x, s2 = as_[rb][nb][2] + bs.x;
                float g3 = ag[rb][nb][3] + bg.y, s3 = as_[rb][nb][3] + bs.y;
                float2 v0, v1;
                v0.x = g0 * (1.f/(1.f + expf(-s0)));
                v0.y = g1 * (1.f/(1.f + expf(-s1)));
                v1.x = g2 * (1.f/(1.f + expf(-s2)));
                v1.y = g3 * (1.f/(1.f + expf(-s3)));
                int base = S_GLU + (jg >> 6)*UNITE + (jg & 63);
                *(__half2*)(smh + base + m0l*PITCH)     = __floats2half2_rn(v0.x, v0.y);
                *(__half2*)(smh + base + (m0l+8)*PITCH) = __floats2half2_rn(v1.x, v1.y);
            }
        }
    }
    __syncthreads();

    // ===== stage 3: h = glu @ W2 + b2 + yenc, + BN stats =====
    {
        float acc[2][4][4];
        #pragma unroll
        for (int rb = 0; rb < 2; rb++)
            #pragma unroll
            for (int nb = 0; nb < 4; nb++)
                #pragma unroll
                for (int j = 0; j < 4; j++) acc[rb][nb][j] = 0.f;

        #pragma unroll 1
        for (int kc = 0; kc < 4; kc++) {
            __syncthreads();
            #pragma unroll
            for (int i = 0; i < 4; i++) {
                int idx = tid + NTHR*i;            // 2048
                int pl  = idx >> 10;
                int rem = idx & 1023;
                int r   = rem >> 3;
                int q   = rem & 7;
                const __half* src = pl ? W2lp : W2hp;
                cp16(smb + (uint32_t)(((pl ? S_BL3 : S_BH3) + r*PITCH + q*8)*2),
                     src + (size_t)r*256 + kc*64 + q*8);
            }
            CP_COMMIT();
            CP_WAIT0();
            __syncthreads();
            #pragma unroll
            for (int kk = 0; kk < 4; kk++) {
                const int kkE = kk*16;
                uint32_t ah[2][4];
                #pragma unroll
                for (int rb = 0; rb < 2; rb++) {
                    int abase = S_GLU + kc*UNITE + (32*wr + 16*rb)*PITCH + kkE + aLaneE;
                    LDSM4(ah[rb], smb + (uint32_t)(abase*2));
                }
                #pragma unroll
                for (int nb2 = 0; nb2 < 2; nb2++) {
                    uint32_t bh[4], bl[4];
                    int bo = (32*wc4 + 16*nb2)*PITCH + kkE + bLaneE;
                    LDSM4(bh, smb + (uint32_t)((S_BH3 + bo)*2));
                    LDSM4(bl, smb + (uint32_t)((S_BL3 + bo)*2));
                    #pragma unroll
                    for (int rb = 0; rb < 2; rb++)
                        #pragma unroll
                        for (int j = 0; j < 2; j++) {
                            float* d = acc[rb][2*nb2 + j];
                            MMA_F16(d, ah[rb], bh[2*j], bh[2*j+1]);
                            MMA_F16(d, ah[rb], bl[2*j], bl[2*j+1]);
                        }
                }
            }
        }

        float cs0[4], cs1[4], cq0[4], cq1[4];
        #pragma unroll
        for (int nb = 0; nb < 4; nb++) { cs0[nb]=0.f; cs1[nb]=0.f; cq0[nb]=0.f; cq1[nb]=0.f; }
        #pragma unroll
        for (int rb = 0; rb < 2; rb++) {
            int m0 = bm + 32*wr + 16*rb + g;
            #pragma unroll
            for (int nb = 0; nb < 4; nb++) {
                int col = 32*wc4 + 8*nb + 2*t;
                float2 bv = *(const float2*)(b2 + col);
                float2 y0 = *(const float2*)(yenc + (size_t)m0*DE + col);
                float2 y1 = *(const float2*)(yenc + (size_t)(m0+8)*DE + col);
                float2 v0, v1;
                v0.x = acc[rb][nb][0] + bv.x + y0.x;
                v0.y = acc[rb][nb][1] + bv.y + y0.y;
                v1.x = acc[rb][nb][2] + bv.x + y1.x;
                v1.y = acc[rb][nb][3] + bv.y + y1.y;
                cs0[nb] += v0.x + v1.x;
                cs1[nb] += v0.y + v1.y;
                cq0[nb] += v0.x*v0.x + v1.x*v1.x;
                cq1[nb] += v0.y*v0.y + v1.y*v1.y;
                *(__half2*)(hout + (size_t)m0*DE + col)     = __floats2half2_rn(v0.x, v0.y);
                *(__half2*)(hout + (size_t)(m0+8)*DE + col) = __floats2half2_rn(v1.x, v1.y);
            }
        }
        #pragma unroll
        for (int nb = 0; nb < 4; nb++) {
            #pragma unroll
            for (int m = 4; m <= 16; m <<= 1) {
                cs0[nb] += __shfl_xor_sync(0xffffffffu, cs0[nb], m);
                cs1[nb] += __shfl_xor_sync(0xffffffffu, cs1[nb], m);
                cq0[nb] += __shfl_xor_sync(0xffffffffu, cq0[nb], m);
                cq1[nb] += __shfl_xor_sync(0xffffffffu, cq1[nb], m);
            }
        }
        __syncthreads();
        float* spart = (float*)smh;
        if (lane < 4) {
            #pragma unroll
            for (int nb = 0; nb < 4; nb++) {
                int col = 32*wc4 + 8*nb + 2*lane;
                spart[wr*128 + col]           = cs0[nb];
                spart[wr*128 + col + 1]       = cs1[nb];
                spart[512 + wr*128 + col]     = cq0[nb];
                spart[512 + wr*128 + col + 1] = cq1[nb];
            }
        }
        __syncthreads();
        if (tid < 128) {
            float s  = spart[tid] + spart[128+tid] + spart[256+tid] + spart[384+tid];
            float s2 = spart[512+tid] + spart[640+tid] + spart[768+tid] + spart[896+tid];
            g_bnpart[blockIdx.y*(2*DE) + tid]      = s;
            g_bnpart[blockIdx.y*(2*DE) + DE + tid] = s2;
        }
    }
}

// ---------------- LRU scan ----------------
__device__ __forceinline__ float2 cstep(float2 lam, float2 s, float2 u) {
    float2 t;
    t.x = fmaf(lam.x, s.x, fmaf(-lam.y, s.y, u.x));
    t.y = fmaf(lam.x, s.y, fmaf( lam.y, s.x, u.y));
    return t;
}
__device__ __forceinline__ float2 ldh2(const uint32_t* p, size_t off) {
    uint32_t r = p[off];
    return __half22float2(*(__half2*)&r);
}
__global__ void scanA_kernel(int blk) {
    int g  = blockIdx.x*256 + threadIdx.x;
    int h  = g & 255;
    int bc = g >> 8;
    int b  = bc >> 4;
    int c  = bc & 15;
    float2 lam = g_lam[blk*HH + h];
    float2 s = make_float2(0.f, 0.f);
    const uint32_t* p = (const uint32_t*)g_bu;
    size_t base = (size_t)(b*TT + c*CLEN)*256 + h;
    #pragma unroll 8
    for (int i = 0; i < CLEN; i++)
        s = cstep(lam, s, ldh2(p, base + (size_t)i*256));
    g_carry[bc*HH + h] = s;
}
__global__ void scanB_kernel(int blk) {
    int b = blockIdx.x;
    int h = threadIdx.x;
    float2 lam = g_lam[blk*HH + h];
    float2 lp = lam;
    #pragma unroll
    for (int i = 0; i < 8; i++) {
        float2 t;
        t.x = lp.x*lp.x - lp.y*lp.y;
        t.y = 2.f*lp.x*lp.y;
        lp = t;
    }
    float2 s = make_float2(0.f, 0.f);
    for (int c = 0; c < NCH; c++) {
        g_inc[(b*NCH + c)*HH + h] = s;
        float2 cr = g_carry[(b*NCH + c)*HH + h];
        s = cstep(lp, s, cr);
    }
}
__global__ void scanC_kernel(int blk) {
    int g  = blockIdx.x*256 + threadIdx.x;
    int h  = g & 255;
    int bc = g >> 8;
    int b  = bc >> 4;
    int c  = bc & 15;
    float2 lam = g_lam[blk*HH + h];
    float2 s = g_inc[bc*HH + h];
    uint32_t* p = (uint32_t*)g_bu;
    size_t base = (size_t)(b*TT + c*CLEN)*256 + h;
    #pragma unroll 8
    for (int i = 0; i < CLEN; i++) {
        size_t off = base + (size_t)i*256;
        s = cstep(lam, s, ldh2(p, off));
        __half2 sv = __floats2half2_rn(s.x, s.y);
        p[off] = *(uint32_t*)&sv;
    }
}

// ---------------- final: mean-pool + head (fp16 h) ----------------
__global__ void final_kernel(const float* __restrict__ Wout,
                             const float* __restrict__ bout,
                             float* __restrict__ out) {
    __shared__ float pooled[DE];
    int b = blockIdx.x;
    int f = threadIdx.x;
    float s = 0.f;
    const __half* p = g_h + (size_t)b*TT*DE + f;
    #pragma unroll 4
    for (int t = 0; t < TT; t++) s += __half2float(p[(size_t)t*DE]);
    pooled[f] = s * (1.f/TT);
    __syncthreads();
    if (f < OD) {
        float acc = bout[f];
        #pragma unroll 4
        for (int d = 0; d < DE; d++) acc = fmaf(pooled[d], Wout[d*OD + f], acc);
        out[b*OD + f] = acc;
    }
}

// ---------------- launch ----------------
#define SMEM_ENC   147456   // f32A, NBT=4
#define SMEM_BU16  184320   // f16A, NBT=8

extern "C" void kernel_launch(void* const* d_in, const int* in_sizes, int n_in,
                              void* d_out, int out_size) {
    const float* x         = (const float*)d_in[0];
    const float* nu_log    = (const float*)d_in[1];
    const float* theta_log = (const float*)d_in[2];
    const float* B_re      = (const float*)d_in[3];
    const float* B_im      = (const float*)d_in[4];
    const float* C_re      = (const float*)d_in[5];
    const float* C_im      = (const float*)d_in[6];
    const float* D_lru     = (const float*)d_in[7];
    const float* W1        = (const float*)d_in[8];
    const float* b1        = (const float*)d_in[9];
    const float* W2        = (const float*)d_in[10];
    const float* b2        = (const float*)d_in[11];
    const float* bn_scale  = (const float*)d_in[12];
    const float* bn_bias   = (const float*)d_in[13];
    const float* W_enc     = (const float*)d_in[14];
    const float* b_enc     = (const float*)d_in[15];
    const float* W_out     = (const float*)d_in[16];
    const float* b_out     = (const float*)d_in[17];
    float* out = (float*)d_out;

    float *yenc, *bubias;
    __half *hh, *bu, *wbfh, *wbfl, *wch, *wcl, *w1h, *w1l, *w2h, *w2l;
    __nv_bfloat16 *weh, *wel;
    cudaGetSymbolAddress((void**)&yenc, g_yenc);
    cudaGetSymbolAddress((void**)&hh,   g_h);
    cudaGetSymbolAddress((void**)&bu,   g_bu);
    cudaGetSymbolAddress((void**)&wbfh, g_WBfh);
    cudaGetSymbolAddress((void**)&wbfl, g_WBfl);
    cudaGetSymbolAddress((void**)&weh,  g_WEh);
    cudaGetSymbolAddress((void**)&wel,  g_WEl);
    cudaGetSymbolAddress((void**)&wch,  g_WCh);
    cudaGetSymbolAddress((void**)&wcl,  g_WCl);
    cudaGetSymbolAddress((void**)&w1h,  g_W1h);
    cudaGetSymbolAddress((void**)&w1l,  g_W1l);
    cudaGetSymbolAddress((void**)&w2h,  g_W2h);
    cudaGetSymbolAddress((void**)&w2l,  g_W2l);
    cudaGetSymbolAddress((void**)&bubias, g_bubias);

    cudaFuncSetAttribute(gemm_mma<64, 128, 0, 0, 0, 2, 1, 4>,  cudaFuncAttributeMaxDynamicSharedMemorySize, SMEM_ENC);
    cudaFuncSetAttribute(gemm_mma<128, 512, 0, 0, 1, 1, 0, 8>, cudaFuncAttributeMaxDynamicSharedMemorySize, SMEM_BU16);
    cudaFuncSetAttribute(mlp_fused, cudaFuncAttributeMaxDynamicSharedMemorySize, SMEM_FUSED);

    prep_lam_kernel<<<NBLKS, HH>>>(nu_log, theta_log);
    prep_WE_kernel<<<(DE*TSD + 255)/256, 256>>>(W_enc);
    prep_WBf_kernel<<<(NBLKS*512*DE + 255)/256, 256>>>(B_re, B_im);

    // encoder: yenc(fp32) + h copy(fp16) = x @ W_enc + b_enc  (+ BN partials for block 0)
    gemm_mma<64, 128, 0, 0, 0, 2, 1, 4><<<dim3(1, NR/128), NTHR, SMEM_ENC>>>(
        x, weh, wel, yenc, b_enc);

    prep_WC_kernel<<<(NBLKS*DE*512 + 255)/256, 256>>>(C_re, C_im);
    prep_W1_kernel<<<(NBLKS*512*DE + 255)/256, 256>>>(W1);
    prep_W2_kernel<<<(NBLKS*DE*256 + 255)/256, 256>>>(W2);

    for (int blk = 0; blk < NBLKS; blk++) {
        bn_stats2_kernel<<<1, 512>>>(bn_scale + blk*DE, bn_bias + blk*DE);
        fold_WB_kernel<<<256, 256>>>(blk);
        fold_bias_kernel<<<1, 512>>>(blk);

        // Bu = h @ (diag(a)WB) + (b.WB)   (fp16 A, 2-term, 256-wide tiles)
        gemm_mma<128, 512, 0, 0, 1, 1, 0, 8><<<dim3(2, NR/128), NTHR, SMEM_BU16>>>(
            hh, wbfh, wbfl, bu, bubias);

        scanA_kernel<<<NR/256, 256>>>(blk);
        scanB_kernel<<<BB, HH>>>(blk);
        scanC_kernel<<<NR/256, 256>>>(blk);

        // fused: cproj + GLU + W2 + residual + BN stats
        mlp_fused<<<dim3(1, NR/128), NTHR, SMEM_FUSED>>>(
            bu,
            wch + (size_t)blk*128*512, wcl + (size_t)blk*128*512,
            w1h + (size_t)blk*512*128, w1l + (size_t)blk*512*128,
            w2h + (size_t)blk*128*256, w2l + (size_t)blk*128*256,
            hh, yenc,
            b1 + (size_t)blk*LDF, b2 + (size_t)blk*DE, D_lru + blk*DE);
    }

    final_kernel<<<BB, DE>>>(W_out, b_out, out);
}

// round 14
// speedup vs baseline: 1.0427x; 1.0427x over previous
#include <cuda_runtime.h>
#include <cuda_bf16.h>
#include <cuda_fp16.h>
#include <math.h>
#include <stdint.h>

// ---------------- problem constants ----------------
#define BB   16
#define TT   4096
#define NR   (BB*TT)
#define TSD  64
#define DE   128
#define HH   256
#define LDF  512
#define LDH  256
#define OD   10
#define NBLKS 6
#define EPSV 1e-5f
#define NCH  16
#define CLEN 256

// ---------------- scratch ----------------
static __device__ __align__(256) float  g_yenc[(size_t)NR*DE];  // fp32 residual anchor
static __device__ __align__(256) __half g_h  [(size_t)NR*DE];   // running hidden, fp16
static __device__ __align__(256) __half g_lru[(size_t)NR*DE];
static __device__ __align__(256) __half g_glu[(size_t)NR*LDH];
static __device__ __align__(256) __half g_bu [(size_t)NR*512];  // Bu -> state (in place), fp16
static __device__ float2 g_lam [NBLKS*HH];
static __device__ float  g_gamma[NBLKS*HH];
static __device__ float  g_bnpart[512*2*DE];
static __device__ float  g_bna[DE];
static __device__ float  g_bnb[DE];
static __device__ float  g_bubias[512];
static __device__ float2 g_carry[BB*NCH*HH];

// weights
static __device__ __align__(256) float  g_WBf[(size_t)NBLKS*512*128]; // gamma-scaled fp32 master
static __device__ __align__(256) __half g_WBfh[512*128];              // per-block BN-folded, fp16 split
static __device__ __align__(256) __half g_WBfl[512*128];
static __device__ __align__(256) __nv_bfloat16 g_WEh[128*64];
static __device__ __align__(256) __nv_bfloat16 g_WEl[128*64];
static __device__ __align__(256) __half g_WCh[(size_t)NBLKS*128*512];
static __device__ __align__(256) __half g_WCl[(size_t)NBLKS*128*512];
static __device__ __align__(256) __half g_W1h[(size_t)NBLKS*512*128];
static __device__ __align__(256) __half g_W1l[(size_t)NBLKS*512*128];
static __device__ __align__(256) __half g_W2h[(size_t)NBLKS*128*256];
static __device__ __align__(256) __half g_W2l[(size_t)NBLKS*128*256];

// ---------------- helpers ----------------
__device__ __forceinline__ uint32_t smem_u32(const void* p) {
    uint32_t a;
    asm("{ .reg .u64 t; cvta.to.shared.u64 t, %1; cvt.u32.u64 %0, t; }" : "=r"(a) : "l"(p));
    return a;
}
__device__ __forceinline__ void cp16(uint32_t dst, const void* src) {
    asm volatile("cp.async.cg.shared.global [%0], [%1], 16;" :: "r"(dst), "l"(src));
}
#define CP_COMMIT() asm volatile("cp.async.commit_group;" ::: "memory")
#define CP_WAIT0()  asm volatile("cp.async.wait_group 0;" ::: "memory")

#define MMA_BF16(d, a, b0, b1) \
    asm volatile("mma.sync.aligned.m16n8k16.row.col.f32.bf16.bf16.f32 " \
        "{%0,%1,%2,%3}, {%4,%5,%6,%7}, {%8,%9}, {%0,%1,%2,%3};" \
        : "+f"((d)[0]), "+f"((d)[1]), "+f"((d)[2]), "+f"((d)[3]) \
        : "r"((a)[0]), "r"((a)[1]), "r"((a)[2]), "r"((a)[3]), "r"(b0), "r"(b1))

#define MMA_F16(d, a, b0, b1) \
    asm volatile("mma.sync.aligned.m16n8k16.row.col.f32.f16.f16.f32 " \
        "{%0,%1,%2,%3}, {%4,%5,%6,%7}, {%8,%9}, {%0,%1,%2,%3};" \
        : "+f"((d)[0]), "+f"((d)[1]), "+f"((d)[2]), "+f"((d)[3]) \
        : "r"((a)[0]), "r"((a)[1]), "r"((a)[2]), "r"((a)[3]), "r"(b0), "r"(b1))

#define LDSM4(r, addr) \
    asm volatile("ldmatrix.sync.aligned.m8n8.x4.shared.b16 {%0,%1,%2,%3}, [%4];" \
        : "=r"((r)[0]), "=r"((r)[1]), "=r"((r)[2]), "=r"((r)[3]) : "r"(addr))

__device__ __forceinline__ void split_store(float v, __nv_bfloat16* hi, __nv_bfloat16* lo, size_t i) {
    __nv_bfloat16 h = __float2bfloat16(v);
    hi[i] = h;
    lo[i] = __float2bfloat16(v - __bfloat162float(h));
}
__device__ __forceinline__ void split_store_h(float v, __half* hi, __half* lo, size_t i) {
    __half h = __float2half_rn(v);
    hi[i] = h;
    lo[i] = __float2half_rn(v - __half2float(h));
}

// ---------------- prep ----------------
__global__ void prep_lam_kernel(const float* __restrict__ nu_log,
                                const float* __restrict__ theta_log) {
    int blk = blockIdx.x;
    int h   = threadIdx.x;
    float nu = nu_log[blk*HH + h];
    float th = theta_log[blk*HH + h];
    float r  = expf(-expf(nu));
    float ang = expf(th);
    float sn, cs;
    sincosf(ang, &sn, &cs);
    float2 lam; lam.x = r*cs; lam.y = r*sn;
    g_lam[blk*HH + h]   = lam;
    g_gamma[blk*HH + h] = sqrtf(fmaxf(1.f - r*r, 1e-8f));
}
__global__ void prep_WBf_kernel(const float* __restrict__ Bre, const float* __restrict__ Bim) {
    int idx = blockIdx.x*256 + threadIdx.x;
    if (idx >= NBLKS*512*DE) return;
    int k = idx & 127;
    int n = (idx >> 7) & 511;
    int blk = idx >> 16;
    int h = n >> 1;
    float g = g_gamma[blk*HH + h];
    g_WBf[idx] = ((n & 1) ? Bim : Bre)[((size_t)blk*HH + h)*DE + k] * g;
}
__global__ void prep_WC_kernel(const float* __restrict__ Cre, const float* __restrict__ Cim) {
    int idx = blockIdx.x*256 + threadIdx.x;
    if (idx >= NBLKS*DE*512) return;
    int k = idx & 511;
    int n = (idx >> 9) & 127;
    int blk = idx >> 16;
    int h = k >> 1;
    float v = (k & 1) ? -Cim[((size_t)blk*DE + n)*HH + h] : Cre[((size_t)blk*DE + n)*HH + h];
    split_store_h(v, g_WCh, g_WCl, idx);
}
__global__ void prep_W1_kernel(const float* __restrict__ W1) {
    int idx = blockIdx.x*256 + threadIdx.x;
    if (idx >= NBLKS*512*DE) return;
    int k = idx & 127;
    int n = (idx >> 7) & 511;
    int blk = idx >> 16;
    split_store_h(W1[((size_t)blk*DE + k)*LDF + n], g_W1h, g_W1l, idx);
}
__global__ void prep_W2_kernel(const float* __restrict__ W2) {
    int idx = blockIdx.x*256 + threadIdx.x;
    if (idx >= NBLKS*DE*256) return;
    int k = idx & 255;
    int n = (idx >> 8) & 127;
    int blk = idx >> 15;
    split_store_h(W2[((size_t)blk*LDH + k)*DE + n], g_W2h, g_W2l, idx);
}
__global__ void prep_WE_kernel(const float* __restrict__ We) {
    int idx = blockIdx.x*256 + threadIdx.x;
    if (idx >= DE*TSD) return;
    int k = idx & 63;
    int n = idx >> 6;
    split_store(We[(size_t)k*DE + n], g_WEh, g_WEl, idx);
}

// ---------------- batchnorm stage-2 + merged BN fold ----------------
__global__ void bn_stats2_kernel(const float* __restrict__ scale,
                                 const float* __restrict__ bias) {
    __shared__ float ss[512], sq[512];
    int tid = threadIdx.x;
    int f = tid & 127;
    int grp = tid >> 7;
    float s = 0.f, s2 = 0.f;
    for (int i = grp; i < 512; i += 4) {
        s  += g_bnpart[i*(2*DE) + f];
        s2 += g_bnpart[i*(2*DE) + DE + f];
    }
    ss[tid] = s;
    sq[tid] = s2;
    __syncthreads();
    if (tid < 128) {
        s  = ss[tid] + ss[128+tid] + ss[256+tid] + ss[384+tid];
        s2 = sq[tid] + sq[128+tid] + sq[256+tid] + sq[384+tid];
        float mean = s * (1.f/NR);
        float var  = s2 * (1.f/NR) - mean*mean;
        float a = scale[tid] * rsqrtf(var + EPSV);
        g_bna[tid] = a;
        g_bnb[tid] = fmaf(-mean, a, bias[tid]);
    }
}
// blocks 0..255: scale+split WB; block 256: fold bias (2 n per thread)
__global__ void fold_kernel(int blk) {
    if (blockIdx.x < 256) {
        int idx = blockIdx.x*256 + threadIdx.x;
        int k = idx & 127;
        float v = g_WBf[(size_t)blk*512*128 + idx] * g_bna[k];
        split_store_h(v, g_WBfh, g_WBfl, idx);
    } else {
        #pragma unroll
        for (int r = 0; r < 2; r++) {
            int n = threadIdx.x + 256*r;
            const float* w = g_WBf + (size_t)blk*512*128 + (size_t)n*128;
            float s = 0.f;
            #pragma unroll 4
            for (int k = 0; k < 128; k++) s = fmaf(g_bnb[k], w[k], s);
            g_bubias[n] = s;
        }
    }
}

// ---------------- GEMM: 512 threads, 16 warps (4x4), variable N tile ----------------
// AF16=0: A fp32 reg-staged -> bf16 split (3-term). AF16=1: A fp16, 2-term fp16 MMA.
// EPI: 0 +bias?; 1 cproj (+(a*aux+b)*d, aux fp16 if AUXH); 2 +bias+aux residual (fp32).
// OUTH: 0 fp32 out; 1 fp16 out; 2 fp32 out + fp16 copy into g_h.
// STATS: per-CTA BN partials (grid.x==1, NBT==4, !DUAL). NBT: n8-tiles per warp.
#define PITCH 72
#define UNITE (128*PITCH)
#define NTHR 512

template<int KDIM, int OUTW, int MODE_A, int EPI, int DUAL, int AF16, int OUTH, int STATS, int NBT, int AUXH>
__global__ void __launch_bounds__(NTHR) gemm_mma(
    const void* __restrict__ Av,
    const void* __restrict__ Bhi_, const void* __restrict__ Blo_,
    void* __restrict__ Cv,
    const float* __restrict__ bias,
    const void* __restrict__ auxv,
    const float* __restrict__ dvec)
{
    constexpr int ABUFS = AF16 ? 1 : 2;
    constexpr int BROWS = (DUAL ? 64 : 32) * NBT;
    constexpr int BUNIT = BROWS * PITCH;
    constexpr int O_AH = 0, O_AL = UNITE;
    constexpr int O_BH = ABUFS*UNITE;
    constexpr int O_BL = O_BH + BUNIT;
    constexpr int STAGE = ABUFS*UNITE + 2*BUNIT;
    constexpr int NCHK = KDIM / 64;
    constexpr int CPB_IT = (BROWS*16)/NTHR;

    extern __shared__ __nv_bfloat16 sm[];
    const uint32_t smb = smem_u32(sm);
    const int tid  = threadIdx.x;
    const int lane = tid & 31;
    const int wid  = tid >> 5;
    const int wr   = wid & 3;
    const int wc4  = wid >> 2;
    const int g    = lane >> 2;
    const int t    = lane & 3;
    const int bm   = blockIdx.y << 7;
    const int bn   = blockIdx.x * (32*NBT);

    const int aLaneE = (lane & 15)*PITCH + (lane >> 4)*8;
    const int bLaneE = (lane & 7)*PITCH + ((lane >> 4) & 1)*(8*PITCH) + ((lane >> 3) & 1)*8;

    float accg[2][NBT][4];
    float accs[DUAL ? 2 : 1][DUAL ? NBT : 1][4];
    #pragma unroll
    for (int rb = 0; rb < 2; rb++)
        #pragma unroll
        for (int nb = 0; nb < NBT; nb++)
            #pragma unroll
            for (int j = 0; j < 4; j++) {
                accg[rb][nb][j] = 0.f;
                if (DUAL) accs[rb][nb][j] = 0.f;
            }

    float4 areg[4];
    auto loadA = [&](int cc) {
        const float* Af = (const float*)Av;
        #pragma unroll
        for (int i = 0; i < 4; i++) {
            int idx = tid + NTHR*i;
            int row = idx >> 4;
            int col4 = (idx & 15) << 2;
            areg[i] = *(const float4*)(Af + (size_t)(bm + row)*KDIM + cc*64 + col4);
        }
    };
    auto storeA = [&](int cc, int so) {
        #pragma unroll
        for (int i = 0; i < 4; i++) {
            int idx = tid + NTHR*i;
            int row = idx >> 4;
            int col4 = (idx & 15) << 2;
            float4 v = areg[i];
            if (MODE_A) {
                float4 aa = *(const float4*)(g_bna + cc*64 + col4);
                float4 ab = *(const float4*)(g_bnb + cc*64 + col4);
                v.x = fmaf(aa.x, v.x, ab.x);
                v.y = fmaf(aa.y, v.y, ab.y);
                v.z = fmaf(aa.z, v.z, ab.z);
                v.w = fmaf(aa.w, v.w, ab.w);
            }
            __nv_bfloat16 h0 = __float2bfloat16(v.x), h1 = __float2bfloat16(v.y);
            __nv_bfloat16 h2 = __float2bfloat16(v.z), h3 = __float2bfloat16(v.w);
            __nv_bfloat16 l0 = __float2bfloat16(v.x - __bfloat162float(h0));
            __nv_bfloat16 l1 = __float2bfloat16(v.y - __bfloat162float(h1));
            __nv_bfloat16 l2 = __float2bfloat16(v.z - __bfloat162float(h2));
            __nv_bfloat16 l3 = __float2bfloat16(v.w - __bfloat162float(h3));
            uint32_t hu0 = ((uint32_t)__bfloat16_as_ushort(h1) << 16) | __bfloat16_as_ushort(h0);
            uint32_t hu1 = ((uint32_t)__bfloat16_as_ushort(h3) << 16) | __bfloat16_as_ushort(h2);
            uint32_t lu0 = ((uint32_t)__bfloat16_as_ushort(l1) << 16) | __bfloat16_as_ushort(l0);
            uint32_t lu1 = ((uint32_t)__bfloat16_as_ushort(l3) << 16) | __bfloat16_as_ushort(l2);
            int off = row*PITCH + col4;
            *(uint2*)(sm + so + O_AH + off) = make_uint2(hu0, hu1);
            *(uint2*)(sm + so + O_AL + off) = make_uint2(lu0, lu1);
        }
    };
    auto cpA16 = [&](int cc, int so) {
        const __half* Ahalf = (const __half*)Av;
        #pragma unroll
        for (int i = 0; i < 2; i++) {
            int idx = tid + NTHR*i;
            int r = idx >> 3;
            int q = idx & 7;
            cp16(smb + (uint32_t)((so + O_AH + r*PITCH + q*8)*2),
                 Ahalf + (size_t)(bm + r)*KDIM + cc*64 + q*8);
        }
    };
    auto cpB = [&](int cc, int so) {
        const __nv_bfloat16* Bh = (const __nv_bfloat16*)Bhi_;
        const __nv_bfloat16* Bl = (const __nv_bfloat16*)Blo_;
        #pragma unroll
        for (int i = 0; i < CPB_IT; i++) {
            int idx = tid + NTHR*i;
            int pl  = idx / (BROWS*8);
            int rem = idx % (BROWS*8);
            int r   = rem >> 3;
            int q   = rem & 7;
            int rowg = DUAL ? (r < BROWS/2 ? bn + r : bn + 256 + (r - BROWS/2)) : (bn + r);
            const __nv_bfloat16* src = pl ? Bl : Bh;
            cp16(smb + (uint32_t)((so + (pl ? O_BL : O_BH) + r*PITCH + q*8)*2),
                 src + (size_t)rowg*KDIM + cc*64 + q*8);
        }
    };

    // prologue
    if (AF16) cpA16(0, 0); else loadA(0);
    cpB(0, 0);
    CP_COMMIT();
    if (!AF16) {
        storeA(0, 0);
        if (NCHK > 1) loadA(1);
    }

    #pragma unroll 1
    for (int c = 0; c < NCHK; c++) {
        const int so = (c & 1)*STAGE;
        CP_WAIT0();
        __syncthreads();
        if (c + 1 < NCHK) {
            const int nso = ((c+1) & 1)*STAGE;
            cpB(c+1, nso);
            if (AF16) cpA16(c+1, nso);
            CP_COMMIT();
            if (!AF16) {
                storeA(c+1, nso);
                if (c + 2 < NCHK) loadA(c+2);
            }
        }

        #pragma unroll
        for (int kk = 0; kk < 4; kk++) {
            const int kkE = kk*16;
            uint32_t ah[2][4], al[2][4];
            #pragma unroll
            for (int rb = 0; rb < 2; rb++) {
                int abase = so + (32*wr + 16*rb)*PITCH + kkE + aLaneE;
                LDSM4(ah[rb], smb + (uint32_t)((O_AH + abase)*2));
                if (!AF16) LDSM4(al[rb], smb + (uint32_t)((O_AL + abase)*2));
            }
            if (!DUAL) {
                #pragma unroll
                for (int nb2 = 0; nb2 < NBT/2; nb2++) {
                    uint32_t bh[4], bl[4];
                    int bbase = so + (8*NBT*wc4 + 16*nb2)*PITCH + kkE + bLaneE;
                    LDSM4(bh, smb + (uint32_t)((O_BH + bbase)*2));
                    LDSM4(bl, smb + (uint32_t)((O_BL + bbase)*2));
                    #pragma unroll
                    for (int rb = 0; rb < 2; rb++)
                        #pragma unroll
                        for (int j = 0; j < 2; j++) {
                            float* d = accg[rb][2*nb2 + j];
                            if (AF16) {
                                MMA_F16(d, ah[rb], bh[2*j], bh[2*j+1]);
                                MMA_F16(d, ah[rb], bl[2*j], bl[2*j+1]);
                            } else {
                                MMA_BF16(d, ah[rb], bh[2*j], bh[2*j+1]);
                                MMA_BF16(d, al[rb], bh[2*j], bh[2*j+1]);
                                MMA_BF16(d, ah[rb], bl[2*j], bl[2*j+1]);
                            }
                        }
                }
            } else {
                #pragma unroll
                for (int nb2 = 0; nb2 < NBT/2; nb2++) {
                    uint32_t bh[4], bl[4], dh[4], el[4];
                    int bbase = so + (8*NBT*wc4 + 16*nb2)*PITCH + kkE + bLaneE;
                    int sbase = bbase + (32*NBT)*PITCH;
                    LDSM4(bh, smb + (uint32_t)((O_BH + bbase)*2));
                    LDSM4(bl, smb + (uint32_t)((O_BL + bbase)*2));
                    LDSM4(dh, smb + (uint32_t)((O_BH + sbase)*2));
                    LDSM4(el, smb + (uint32_t)((O_BL + sbase)*2));
                    #pragma unroll
                    for (int rb = 0; rb < 2; rb++)
                        #pragma unroll
                        for (int j = 0; j < 2; j++) {
                            float* dg = accg[rb][2*nb2 + j];
                            float* ds = accs[rb][2*nb2 + j];
                            if (AF16) {
                                MMA_F16(dg, ah[rb], bh[2*j], bh[2*j+1]);
                                MMA_F16(dg, ah[rb], bl[2*j], bl[2*j+1]);
                                MMA_F16(ds, ah[rb], dh[2*j], dh[2*j+1]);
                                MMA_F16(ds, ah[rb], el[2*j], el[2*j+1]);
                            } else {
                                MMA_BF16(dg, ah[rb], bh[2*j], bh[2*j+1]);
                                MMA_BF16(dg, al[rb], bh[2*j], bh[2*j+1]);
                                MMA_BF16(dg, ah[rb], bl[2*j], bl[2*j+1]);
                                MMA_BF16(ds, ah[rb], dh[2*j], dh[2*j+1]);
                                MMA_BF16(ds, al[rb], dh[2*j], dh[2*j+1]);
                                MMA_BF16(ds, ah[rb], el[2*j], el[2*j+1]);
                            }
                        }
                }
            }
        }
    }

    // ---- epilogue ----
    float cs0[STATS ? NBT : 1], cs1[STATS ? NBT : 1], cq0[STATS ? NBT : 1], cq1[STATS ? NBT : 1];
    if (STATS) {
        #pragma unroll
        for (int nb = 0; nb < NBT; nb++) { cs0[nb]=0.f; cs1[nb]=0.f; cq0[nb]=0.f; cq1[nb]=0.f; }
    }
    #pragma unroll
    for (int rb = 0; rb < 2; rb++) {
        int m0 = bm + 32*wr + 16*rb + g;
        #pragma unroll
        for (int nb = 0; nb < NBT; nb++) {
            if (!DUAL) {
                int col = bn + 8*NBT*wc4 + 8*nb + 2*t;
                float2 v0 = make_float2(accg[rb][nb][0], accg[rb][nb][1]);
                float2 v1 = make_float2(accg[rb][nb][2], accg[rb][nb][3]);
                if (EPI == 0) {
                    if (bias != nullptr) {
                        float2 bv = *(const float2*)(bias + col);
                        v0.x += bv.x; v0.y += bv.y; v1.x += bv.x; v1.y += bv.y;
                    }
                } else if (EPI == 1) {
                    float2 aa = *(const float2*)(g_bna + col);
                    float2 ab = *(const float2*)(g_bnb + col);
                    float2 dv = *(const float2*)(dvec + col);
                    float2 h0, h1;
                    if (AUXH) {
                        const __half* ah2 = (const __half*)auxv;
                        h0 = __half22float2(*(const __half2*)(ah2 + (size_t)m0*DE + col));
                        h1 = __half22float2(*(const __half2*)(ah2 + (size_t)(m0+8)*DE + col));
                    } else {
                        const float* af = (const float*)auxv;
                        h0 = *(const float2*)(af + (size_t)m0*DE + col);
                        h1 = *(const float2*)(af + (size_t)(m0+8)*DE + col);
                    }
                    v0.x += fmaf(aa.x, h0.x, ab.x)*dv.x;
                    v0.y += fmaf(aa.y, h0.y, ab.y)*dv.y;
                    v1.x += fmaf(aa.x, h1.x, ab.x)*dv.x;
                    v1.y += fmaf(aa.y, h1.y, ab.y)*dv.y;
                } else if (EPI == 2) {
                    float2 bv = *(const float2*)(bias + col);
                    const float* af = (const float*)auxv;
                    float2 y0 = *(const float2*)(af + (size_t)m0*OUTW + col);
                    float2 y1 = *(const float2*)(af + (size_t)(m0+8)*OUTW + col);
                    v0.x += bv.x + y0.x; v0.y += bv.y + y0.y;
                    v1.x += bv.x + y1.x; v1.y += bv.y + y1.y;
                }
                if (STATS) {
                    cs0[nb] += v0.x + v1.x;
                    cs1[nb] += v0.y + v1.y;
                    cq0[nb] += v0.x*v0.x + v1.x*v1.x;
                    cq1[nb] += v0.y*v0.y + v1.y*v1.y;
                }
                if (OUTH == 1) {
                    __half* Ch = (__half*)Cv;
                    *(__half2*)(Ch + (size_t)m0*OUTW + col)     = __floats2half2_rn(v0.x, v0.y);
                    *(__half2*)(Ch + (size_t)(m0+8)*OUTW + col) = __floats2half2_rn(v1.x, v1.y);
                } else if (OUTH == 2) {
                    float* Cf = (float*)Cv;
                    *(float2*)(Cf + (size_t)m0*OUTW + col)     = v0;
                    *(float2*)(Cf + (size_t)(m0+8)*OUTW + col) = v1;
                    *(__half2*)(g_h + (size_t)m0*OUTW + col)     = __floats2half2_rn(v0.x, v0.y);
                    *(__half2*)(g_h + (size_t)(m0+8)*OUTW + col) = __floats2half2_rn(v1.x, v1.y);
                } else {
                    float* Cf = (float*)Cv;
                    *(float2*)(Cf + (size_t)m0*OUTW + col)     = v0;
                    *(float2*)(Cf + (size_t)(m0+8)*OUTW + col) = v1;
                }
            } else {
                int jc = bn + 8*NBT*wc4 + 8*nb + 2*t;
                float2 bg = *(const float2*)(bias + jc);
                float2 bs = *(const float2*)(bias + 256 + jc);
                float g0 = accg[rb][nb][0] + bg.x, s0 = accs[rb][nb][0] + bs.x;
                float g1 = accg[rb][nb][1] + bg.y, s1 = accs[rb][nb][1] + bs.y;
                float g2 = accg[rb][nb][2] + bg.x, s2 = accs[rb][nb][2] + bs.x;
                float g3 = accg[rb][nb][3] + bg.y, s3 = accs[rb][nb][3] + bs.y;
                float2 v0, v1;
                v0.x = g0 * (1.f/(1.f + expf(-s0)));
                v0.y = g1 * (1.f/(1.f + expf(-s1)));
                v1.x = g2 * (1.f/(1.f + expf(-s2)));
                v1.y = g3 * (1.f/(1.f + expf(-s3)));
                __half* Ch = (__half*)Cv;
                *(__half2*)(Ch + (size_t)m0*OUTW + jc)     = __floats2half2_rn(v0.x, v0.y);
                *(__half2*)(Ch + (size_t)(m0+8)*OUTW + jc) = __floats2half2_rn(v1.x, v1.y);
            }
        }
    }

    if (STATS && !DUAL) {
        #pragma unroll
        for (int nb = 0; nb < NBT; nb++) {
            #pragma unroll
            for (int m = 4; m <= 16; m <<= 1) {
                cs0[nb] += __shfl_xor_sync(0xffffffffu, cs0[nb], m);
                cs1[nb] += __shfl_xor_sync(0xffffffffu, cs1[nb], m);
                cq0[nb] += __shfl_xor_sync(0xffffffffu, cq0[nb], m);
                cq1[nb] += __shfl_xor_sync(0xffffffffu, cq1[nb], m);
            }
        }
        __syncthreads();
        float* spart = (float*)sm;
        if (lane < 4) {
            #pragma unroll
            for (int nb = 0; nb < NBT; nb++) {
                int col = 8*NBT*wc4 + 8*nb + 2*lane;
                spart[wr*128 + col]           = cs0[nb];
                spart[wr*128 + col + 1]       = cs1[nb];
                spart[512 + wr*128 + col]     = cq0[nb];
                spart[512 + wr*128 + col + 1] = cq1[nb];
            }
        }
        __syncthreads();
        if (tid < 128) {
            float s  = spart[tid] + spart[128+tid] + spart[256+tid] + spart[384+tid];
            float s2 = spart[512+tid] + spart[640+tid] + spart[768+tid] + spart[896+tid];
            g_bnpart[blockIdx.y*(2*DE) + tid]      = s;
            g_bnpart[blockIdx.y*(2*DE) + DE + tid] = s2;
        }
    }
}

// ---------------- LRU scan (fp16 Bu in, in-place fp16 state out) ----------------
__device__ __forceinline__ float2 cstep(float2 lam, float2 s, float2 u) {
    float2 t;
    t.x = fmaf(lam.x, s.x, fmaf(-lam.y, s.y, u.x));
    t.y = fmaf(lam.x, s.y, fmaf( lam.y, s.x, u.y));
    return t;
}
__device__ __forceinline__ float2 ldh2(const uint32_t* p, size_t off) {
    uint32_t r = p[off];
    return __half22float2(*(__half2*)&r);
}
__global__ void scanA_kernel(int blk) {
    int g  = blockIdx.x*256 + threadIdx.x;
    int h  = g & 255;
    int bc = g >> 8;
    int b  = bc >> 4;
    int c  = bc & 15;
    float2 lam = g_lam[blk*HH + h];
    float2 s = make_float2(0.f, 0.f);
    const uint32_t* p = (const uint32_t*)g_bu;
    size_t base = (size_t)(b*TT + c*CLEN)*256 + h;
    #pragma unroll 8
    for (int i = 0; i < CLEN; i++)
        s = cstep(lam, s, ldh2(p, base + (size_t)i*256));
    g_carry[bc*HH + h] = s;
}
// scanC with inline prefix (replaces scanB): inc = sum_{j<c} lam^{256*(c-1-j)} * carry[j]
__global__ void scanC_kernel(int blk) {
    int g  = blockIdx.x*256 + threadIdx.x;
    int h  = g & 255;
    int bc = g >> 8;
    int b  = bc >> 4;
    int c  = bc & 15;
    float2 lam = g_lam[blk*HH + h];
    // lam^256 via 8 squarings
    float2 lp = lam;
    #pragma unroll
    for (int i = 0; i < 8; i++) {
        float2 tt;
        tt.x = lp.x*lp.x - lp.y*lp.y;
        tt.y = 2.f*lp.x*lp.y;
        lp = tt;
    }
    float2 s = make_float2(0.f, 0.f);
    for (int j = 0; j < c; j++) {
        float2 cr = g_carry[(b*NCH + j)*HH + h];
        s = cstep(lp, s, cr);
    }
    uint32_t* p = (uint32_t*)g_bu;
    size_t base = (size_t)(b*TT + c*CLEN)*256 + h;
    #pragma unroll 8
    for (int i = 0; i < CLEN; i++) {
        size_t off = base + (size_t)i*256;
        s = cstep(lam, s, ldh2(p, off));
        __half2 sv = __floats2half2_rn(s.x, s.y);
        p[off] = *(uint32_t*)&sv;
    }
}

// ---------------- final: mean-pool + head (fp16 h) ----------------
__global__ void final_kernel(const float* __restrict__ Wout,
                             const float* __restrict__ bout,
                             float* __restrict__ out) {
    __shared__ float pooled[DE];
    int b = blockIdx.x;
    int f = threadIdx.x;
    float s = 0.f;
    const __half* p = g_h + (size_t)b*TT*DE + f;
    #pragma unroll 4
    for (int t = 0; t < TT; t++) s += __half2float(p[(size_t)t*DE]);
    pooled[f] = s * (1.f/TT);
    __syncthreads();
    if (f < OD) {
        float acc = bout[f];
        #pragma unroll 4
        for (int d = 0; d < DE; d++) acc = fmaf(pooled[d], Wout[d*OD + f], acc);
        out[b*OD + f] = acc;
    }
}

// ---------------- launch ----------------
#define SMEM_ENC   147456   // f32A, NBT=4
#define SMEM_BU16  184320   // f16A, NBT=8
#define SMEM_F16N4 110592   // f16A, NBT=4
#define SMEM_GLU   184320   // f16A, DUAL NBT=4

extern "C" void kernel_launch(void* const* d_in, const int* in_sizes, int n_in,
                              void* d_out, int out_size) {
    const float* x         = (const float*)d_in[0];
    const float* nu_log    = (const float*)d_in[1];
    const float* theta_log = (const float*)d_in[2];
    const float* B_re      = (const float*)d_in[3];
    const float* B_im      = (const float*)d_in[4];
    const float* C_re      = (const float*)d_in[5];
    const float* C_im      = (const float*)d_in[6];
    const float* D_lru     = (const float*)d_in[7];
    const float* W1        = (const float*)d_in[8];
    const float* b1        = (const float*)d_in[9];
    const float* W2        = (const float*)d_in[10];
    const float* b2        = (const float*)d_in[11];
    const float* bn_scale  = (const float*)d_in[12];
    const float* bn_bias   = (const float*)d_in[13];
    const float* W_enc     = (const float*)d_in[14];
    const float* b_enc     = (const float*)d_in[15];
    const float* W_out     = (const float*)d_in[16];
    const float* b_out     = (const float*)d_in[17];
    float* out = (float*)d_out;

    float *yenc, *bubias;
    __half *hh, *bu, *lru, *glu, *wbfh, *wbfl, *wch, *wcl, *w1h, *w1l, *w2h, *w2l;
    __nv_bfloat16 *weh, *wel;
    cudaGetSymbolAddress((void**)&yenc, g_yenc);
    cudaGetSymbolAddress((void**)&hh,   g_h);
    cudaGetSymbolAddress((void**)&bu,   g_bu);
    cudaGetSymbolAddress((void**)&lru,  g_lru);
    cudaGetSymbolAddress((void**)&glu,  g_glu);
    cudaGetSymbolAddress((void**)&wbfh, g_WBfh);
    cudaGetSymbolAddress((void**)&wbfl, g_WBfl);
    cudaGetSymbolAddress((void**)&weh,  g_WEh);
    cudaGetSymbolAddress((void**)&wel,  g_WEl);
    cudaGetSymbolAddress((void**)&wch,  g_WCh);
    cudaGetSymbolAddress((void**)&wcl,  g_WCl);
    cudaGetSymbolAddress((void**)&w1h,  g_W1h);
    cudaGetSymbolAddress((void**)&w1l,  g_W1l);
    cudaGetSymbolAddress((void**)&w2h,  g_W2h);
    cudaGetSymbolAddress((void**)&w2l,  g_W2l);
    cudaGetSymbolAddress((void**)&bubias, g_bubias);

    cudaFuncSetAttribute(gemm_mma<64, 128, 0, 0, 0, 0, 2, 1, 4, 0>,  cudaFuncAttributeMaxDynamicSharedMemorySize, SMEM_ENC);
    cudaFuncSetAttribute(gemm_mma<128, 512, 0, 0, 0, 1, 1, 0, 8, 0>, cudaFuncAttributeMaxDynamicSharedMemorySize, SMEM_BU16);
    cudaFuncSetAttribute(gemm_mma<512, 128, 0, 1, 0, 1, 1, 0, 4, 1>, cudaFuncAttributeMaxDynamicSharedMemorySize, SMEM_F16N4);
    cudaFuncSetAttribute(gemm_mma<128, 256, 0, 0, 1, 1, 1, 0, 4, 0>, cudaFuncAttributeMaxDynamicSharedMemorySize, SMEM_GLU);
    cudaFuncSetAttribute(gemm_mma<256, 128, 0, 2, 0, 1, 1, 1, 4, 0>, cudaFuncAttributeMaxDynamicSharedMemorySize, SMEM_F16N4);

    prep_lam_kernel<<<NBLKS, HH>>>(nu_log, theta_log);
    prep_WE_kernel<<<(DE*TSD + 255)/256, 256>>>(W_enc);
    prep_WBf_kernel<<<(NBLKS*512*DE + 255)/256, 256>>>(B_re, B_im);

    // encoder: yenc(fp32) + h copy(fp16) = x @ W_enc + b_enc  (+ BN partials for block 0)
    gemm_mma<64, 128, 0, 0, 0, 0, 2, 1, 4, 0><<<dim3(1, NR/128), NTHR, SMEM_ENC>>>(
        x, weh, wel, yenc, b_enc, nullptr, nullptr);

    prep_WC_kernel<<<(NBLKS*DE*512 + 255)/256, 256>>>(C_re, C_im);
    prep_W1_kernel<<<(NBLKS*512*DE + 255)/256, 256>>>(W1);
    prep_W2_kernel<<<(NBLKS*DE*256 + 255)/256, 256>>>(W2);

    for (int blk = 0; blk < NBLKS; blk++) {
        bn_stats2_kernel<<<1, 512>>>(bn_scale + blk*DE, bn_bias + blk*DE);
        fold_kernel<<<257, 256>>>(blk);

        // Bu = h @ (diag(a)WB) + (b.WB)   (fp16 A, 2-term, 256-wide tiles)
        gemm_mma<128, 512, 0, 0, 0, 1, 1, 0, 8, 0><<<dim3(2, NR/128), NTHR, SMEM_BU16>>>(
            hh, wbfh, wbfl, bu, bubias, nullptr, nullptr);

        scanA_kernel<<<NR/256, 256>>>(blk);
        scanC_kernel<<<NR/256, 256>>>(blk);

        // lru = Re(state @ C) + BN(h) * D   (aux h fp16)
        gemm_mma<512, 128, 0, 1, 0, 1, 1, 0, 4, 1><<<dim3(1, NR/128), NTHR, SMEM_F16N4>>>(
            bu, wch + (size_t)blk*128*512, wcl + (size_t)blk*128*512,
            lru, nullptr, hh, D_lru + blk*DE);

        // glu = GLU(lru @ W1 + b1)
        gemm_mma<128, 256, 0, 0, 1, 1, 1, 0, 4, 0><<<dim3(2, NR/128), NTHR, SMEM_GLU>>>(
            lru, w1h + (size_t)blk*512*128, w1l + (size_t)blk*512*128,
            glu, b1 + (size_t)blk*LDF, nullptr, nullptr);

        // h(fp16) = glu @ W2 + b2 + yenc(fp32)  (+ BN partials for next block)
        gemm_mma<256, 128, 0, 2, 0, 1, 1, 1, 4, 0><<<dim3(1, NR/128), NTHR, SMEM_F16N4>>>(
            glu, w2h + (size_t)blk*128*256, w2l + (size_t)blk*128*256,
            hh, b2 + blk*DE, yenc, nullptr);
    }

    final_kernel<<<BB, DE>>>(W_out, b_out, out);
}

// round 15
// speedup vs baseline: 1.0634x; 1.0198x over previous
#include <cuda_runtime.h>
#include <cuda_bf16.h>
#include <cuda_fp16.h>
#include <math.h>
#include <stdint.h>

// ---------------- problem constants ----------------
#define BB   16
#define TT   4096
#define NR   (BB*TT)
#define TSD  64
#define DE   128
#define HH   256
#define LDF  512
#define LDH  256
#define OD   10
#define NBLKS 6
#define EPSV 1e-5f
#define NCH  16
#define CLEN 256

// ---------------- scratch ----------------
static __device__ __align__(256) float  g_yenc[(size_t)NR*DE];  // fp32 residual anchor
static __device__ __align__(256) __half g_h  [(size_t)NR*DE];   // running hidden, fp16
static __device__ __align__(256) __half g_lru[(size_t)NR*DE];
static __device__ __align__(256) __half g_glu[(size_t)NR*LDH];
static __device__ __align__(256) __half g_bu [(size_t)NR*512];  // Bu -> state (in place), fp16
static __device__ float2 g_lam [NBLKS*HH];
static __device__ float  g_gamma[NBLKS*HH];
static __device__ float  g_bnpart[512*2*DE];
static __device__ float  g_bna[DE];
static __device__ float  g_bnb[DE];
static __device__ float  g_bubias[512];
static __device__ float2 g_carry[BB*NCH*HH];

// weights
static __device__ __align__(256) float  g_WBf[(size_t)NBLKS*512*128]; // gamma-scaled fp32 master
static __device__ __align__(256) __half g_WBfh[512*128];              // per-block BN-folded, fp16 split
static __device__ __align__(256) __half g_WBfl[512*128];
static __device__ __align__(256) __nv_bfloat16 g_WEh[128*64];
static __device__ __align__(256) __nv_bfloat16 g_WEl[128*64];
static __device__ __align__(256) __half g_WCh[(size_t)NBLKS*128*512];
static __device__ __align__(256) __half g_WCl[(size_t)NBLKS*128*512];
static __device__ __align__(256) __half g_W1h[(size_t)NBLKS*512*128];
static __device__ __align__(256) __half g_W1l[(size_t)NBLKS*512*128];
static __device__ __align__(256) __half g_W2h[(size_t)NBLKS*128*256];
static __device__ __align__(256) __half g_W2l[(size_t)NBLKS*128*256];

// ---------------- helpers ----------------
__device__ __forceinline__ uint32_t smem_u32(const void* p) {
    uint32_t a;
    asm("{ .reg .u64 t; cvta.to.shared.u64 t, %1; cvt.u32.u64 %0, t; }" : "=r"(a) : "l"(p));
    return a;
}
__device__ __forceinline__ void cp16(uint32_t dst, const void* src) {
    asm volatile("cp.async.cg.shared.global [%0], [%1], 16;" :: "r"(dst), "l"(src));
}
#define CP_COMMIT() asm volatile("cp.async.commit_group;" ::: "memory")
#define CP_WAIT0()  asm volatile("cp.async.wait_group 0;" ::: "memory")

#define MMA_BF16(d, a, b0, b1) \
    asm volatile("mma.sync.aligned.m16n8k16.row.col.f32.bf16.bf16.f32 " \
        "{%0,%1,%2,%3}, {%4,%5,%6,%7}, {%8,%9}, {%0,%1,%2,%3};" \
        : "+f"((d)[0]), "+f"((d)[1]), "+f"((d)[2]), "+f"((d)[3]) \
        : "r"((a)[0]), "r"((a)[1]), "r"((a)[2]), "r"((a)[3]), "r"(b0), "r"(b1))

#define MMA_F16(d, a, b0, b1) \
    asm volatile("mma.sync.aligned.m16n8k16.row.col.f32.f16.f16.f32 " \
        "{%0,%1,%2,%3}, {%4,%5,%6,%7}, {%8,%9}, {%0,%1,%2,%3};" \
        : "+f"((d)[0]), "+f"((d)[1]), "+f"((d)[2]), "+f"((d)[3]) \
        : "r"((a)[0]), "r"((a)[1]), "r"((a)[2]), "r"((a)[3]), "r"(b0), "r"(b1))

#define LDSM4(r, addr) \
    asm volatile("ldmatrix.sync.aligned.m8n8.x4.shared.b16 {%0,%1,%2,%3}, [%4];" \
        : "=r"((r)[0]), "=r"((r)[1]), "=r"((r)[2]), "=r"((r)[3]) : "r"(addr))

__device__ __forceinline__ void split_store(float v, __nv_bfloat16* hi, __nv_bfloat16* lo, size_t i) {
    __nv_bfloat16 h = __float2bfloat16(v);
    hi[i] = h;
    lo[i] = __float2bfloat16(v - __bfloat162float(h));
}
__device__ __forceinline__ void split_store_h(float v, __half* hi, __half* lo, size_t i) {
    __half h = __float2half_rn(v);
    hi[i] = h;
    lo[i] = __float2half_rn(v - __half2float(h));
}

// ---------------- prep ----------------
__global__ void prep_lam_kernel(const float* __restrict__ nu_log,
                                const float* __restrict__ theta_log) {
    int blk = blockIdx.x;
    int h   = threadIdx.x;
    float nu = nu_log[blk*HH + h];
    float th = theta_log[blk*HH + h];
    float r  = expf(-expf(nu));
    float ang = expf(th);
    float sn, cs;
    sincosf(ang, &sn, &cs);
    float2 lam; lam.x = r*cs; lam.y = r*sn;
    g_lam[blk*HH + h]   = lam;
    g_gamma[blk*HH + h] = sqrtf(fmaxf(1.f - r*r, 1e-8f));
}
__global__ void prep_WBf_kernel(const float* __restrict__ Bre, const float* __restrict__ Bim) {
    int idx = blockIdx.x*256 + threadIdx.x;
    if (idx >= NBLKS*512*DE) return;
    int k = idx & 127;
    int n = (idx >> 7) & 511;
    int blk = idx >> 16;
    int h = n >> 1;
    float g = g_gamma[blk*HH + h];
    g_WBf[idx] = ((n & 1) ? Bim : Bre)[((size_t)blk*HH + h)*DE + k] * g;
}
__global__ void prep_WC_kernel(const float* __restrict__ Cre, const float* __restrict__ Cim) {
    int idx = blockIdx.x*256 + threadIdx.x;
    if (idx >= NBLKS*DE*512) return;
    int k = idx & 511;
    int n = (idx >> 9) & 127;
    int blk = idx >> 16;
    int h = k >> 1;
    float v = (k & 1) ? -Cim[((size_t)blk*DE + n)*HH + h] : Cre[((size_t)blk*DE + n)*HH + h];
    split_store_h(v, g_WCh, g_WCl, idx);
}
__global__ void prep_W1_kernel(const float* __restrict__ W1) {
    int idx = blockIdx.x*256 + threadIdx.x;
    if (idx >= NBLKS*512*DE) return;
    int k = idx & 127;
    int n = (idx >> 7) & 511;
    int blk = idx >> 16;
    split_store_h(W1[((size_t)blk*DE + k)*LDF + n], g_W1h, g_W1l, idx);
}
__global__ void prep_W2_kernel(const float* __restrict__ W2) {
    int idx = blockIdx.x*256 + threadIdx.x;
    if (idx >= NBLKS*DE*256) return;
    int k = idx & 255;
    int n = (idx >> 8) & 127;
    int blk = idx >> 15;
    split_store_h(W2[((size_t)blk*LDH + k)*DE + n], g_W2h, g_W2l, idx);
}
__global__ void prep_WE_kernel(const float* __restrict__ We) {
    int idx = blockIdx.x*256 + threadIdx.x;
    if (idx >= DE*TSD) return;
    int k = idx & 63;
    int n = idx >> 6;
    split_store(We[(size_t)k*DE + n], g_WEh, g_WEl, idx);
}

// ---------------- batchnorm stage-2 + merged BN fold ----------------
__global__ void bn_stats2_kernel(const float* __restrict__ scale,
                                 const float* __restrict__ bias) {
    __shared__ float ss[512], sq[512];
    int tid = threadIdx.x;
    int f = tid & 127;
    int grp = tid >> 7;
    float s = 0.f, s2 = 0.f;
    for (int i = grp; i < 512; i += 4) {
        s  += g_bnpart[i*(2*DE) + f];
        s2 += g_bnpart[i*(2*DE) + DE + f];
    }
    ss[tid] = s;
    sq[tid] = s2;
    __syncthreads();
    if (tid < 128) {
        s  = ss[tid] + ss[128+tid] + ss[256+tid] + ss[384+tid];
        s2 = sq[tid] + sq[128+tid] + sq[256+tid] + sq[384+tid];
        float mean = s * (1.f/NR);
        float var  = s2 * (1.f/NR) - mean*mean;
        float a = scale[tid] * rsqrtf(var + EPSV);
        g_bna[tid] = a;
        g_bnb[tid] = fmaf(-mean, a, bias[tid]);
    }
}
// blocks 0..255: scale+split WB; block 256: fold bias (2 n per thread)
__global__ void fold_kernel(int blk) {
    if (blockIdx.x < 256) {
        int idx = blockIdx.x*256 + threadIdx.x;
        int k = idx & 127;
        float v = g_WBf[(size_t)blk*512*128 + idx] * g_bna[k];
        split_store_h(v, g_WBfh, g_WBfl, idx);
    } else {
        #pragma unroll
        for (int r = 0; r < 2; r++) {
            int n = threadIdx.x + 256*r;
            const float* w = g_WBf + (size_t)blk*512*128 + (size_t)n*128;
            float s = 0.f;
            #pragma unroll 4
            for (int k = 0; k < 128; k++) s = fmaf(g_bnb[k], w[k], s);
            g_bubias[n] = s;
        }
    }
}

// ---------------- GEMM: 512 threads, 16 warps (4x4), variable N tile ----------------
// AF16=0: A fp32 reg-staged -> bf16 split (3-term). AF16=1: A fp16, 2-term fp16 MMA.
// EPI: 0 +bias?; 1 cproj (+(a*aux+b)*d, aux fp16 if AUXH); 2 +bias+aux residual (fp32).
// OUTH: 0 fp32 out; 1 fp16 out; 2 fp32 out + fp16 copy into g_h.
// STATS: per-CTA BN partials (grid.x==1, NBT==4, !DUAL). NBT: n8-tiles per warp.
// MINB: min blocks/SM (2 for the 110KB-smem kernels -> co-resident CTAs).
#define PITCH 72
#define UNITE (128*PITCH)
#define NTHR 512

template<int KDIM, int OUTW, int MODE_A, int EPI, int DUAL, int AF16, int OUTH, int STATS, int NBT, int AUXH, int MINB>
__global__ void __launch_bounds__(NTHR, MINB) gemm_mma(
    const void* __restrict__ Av,
    const void* __restrict__ Bhi_, const void* __restrict__ Blo_,
    void* __restrict__ Cv,
    const float* __restrict__ bias,
    const void* __restrict__ auxv,
    const float* __restrict__ dvec)
{
    constexpr int ABUFS = AF16 ? 1 : 2;
    constexpr int BROWS = (DUAL ? 64 : 32) * NBT;
    constexpr int BUNIT = BROWS * PITCH;
    constexpr int O_AH = 0, O_AL = UNITE;
    constexpr int O_BH = ABUFS*UNITE;
    constexpr int O_BL = O_BH + BUNIT;
    constexpr int STAGE = ABUFS*UNITE + 2*BUNIT;
    constexpr int NCHK = KDIM / 64;
    constexpr int CPB_IT = (BROWS*16)/NTHR;

    extern __shared__ __nv_bfloat16 sm[];
    const uint32_t smb = smem_u32(sm);
    const int tid  = threadIdx.x;
    const int lane = tid & 31;
    const int wid  = tid >> 5;
    const int wr   = wid & 3;
    const int wc4  = wid >> 2;
    const int g    = lane >> 2;
    const int t    = lane & 3;
    const int bm   = blockIdx.y << 7;
    const int bn   = blockIdx.x * (32*NBT);

    const int aLaneE = (lane & 15)*PITCH + (lane >> 4)*8;
    const int bLaneE = (lane & 7)*PITCH + ((lane >> 4) & 1)*(8*PITCH) + ((lane >> 3) & 1)*8;

    float accg[2][NBT][4];
    float accs[DUAL ? 2 : 1][DUAL ? NBT : 1][4];
    #pragma unroll
    for (int rb = 0; rb < 2; rb++)
        #pragma unroll
        for (int nb = 0; nb < NBT; nb++)
            #pragma unroll
            for (int j = 0; j < 4; j++) {
                accg[rb][nb][j] = 0.f;
                if (DUAL) accs[rb][nb][j] = 0.f;
            }

    float4 areg[4];
    auto loadA = [&](int cc) {
        const float* Af = (const float*)Av;
        #pragma unroll
        for (int i = 0; i < 4; i++) {
            int idx = tid + NTHR*i;
            int row = idx >> 4;
            int col4 = (idx & 15) << 2;
            areg[i] = *(const float4*)(Af + (size_t)(bm + row)*KDIM + cc*64 + col4);
        }
    };
    auto storeA = [&](int cc, int so) {
        #pragma unroll
        for (int i = 0; i < 4; i++) {
            int idx = tid + NTHR*i;
            int row = idx >> 4;
            int col4 = (idx & 15) << 2;
            float4 v = areg[i];
            if (MODE_A) {
                float4 aa = *(const float4*)(g_bna + cc*64 + col4);
                float4 ab = *(const float4*)(g_bnb + cc*64 + col4);
                v.x = fmaf(aa.x, v.x, ab.x);
                v.y = fmaf(aa.y, v.y, ab.y);
                v.z = fmaf(aa.z, v.z, ab.z);
                v.w = fmaf(aa.w, v.w, ab.w);
            }
            __nv_bfloat16 h0 = __float2bfloat16(v.x), h1 = __float2bfloat16(v.y);
            __nv_bfloat16 h2 = __float2bfloat16(v.z), h3 = __float2bfloat16(v.w);
            __nv_bfloat16 l0 = __float2bfloat16(v.x - __bfloat162float(h0));
            __nv_bfloat16 l1 = __float2bfloat16(v.y - __bfloat162float(h1));
            __nv_bfloat16 l2 = __float2bfloat16(v.z - __bfloat162float(h2));
            __nv_bfloat16 l3 = __float2bfloat16(v.w - __bfloat162float(h3));
            uint32_t hu0 = ((uint32_t)__bfloat16_as_ushort(h1) << 16) | __bfloat16_as_ushort(h0);
            uint32_t hu1 = ((uint32_t)__bfloat16_as_ushort(h3) << 16) | __bfloat16_as_ushort(h2);
            uint32_t lu0 = ((uint32_t)__bfloat16_as_ushort(l1) << 16) | __bfloat16_as_ushort(l0);
            uint32_t lu1 = ((uint32_t)__bfloat16_as_ushort(l3) << 16) | __bfloat16_as_ushort(l2);
            int off = row*PITCH + col4;
            *(uint2*)(sm + so + O_AH + off) = make_uint2(hu0, hu1);
            *(uint2*)(sm + so + O_AL + off) = make_uint2(lu0, lu1);
        }
    };
    auto cpA16 = [&](int cc, int so) {
        const __half* Ahalf = (const __half*)Av;
        #pragma unroll
        for (int i = 0; i < 2; i++) {
            int idx = tid + NTHR*i;
            int r = idx >> 3;
            int q = idx & 7;
            cp16(smb + (uint32_t)((so + O_AH + r*PITCH + q*8)*2),
                 Ahalf + (size_t)(bm + r)*KDIM + cc*64 + q*8);
        }
    };
    auto cpB = [&](int cc, int so) {
        const __nv_bfloat16* Bh = (const __nv_bfloat16*)Bhi_;
        const __nv_bfloat16* Bl = (const __nv_bfloat16*)Blo_;
        #pragma unroll
        for (int i = 0; i < CPB_IT; i++) {
            int idx = tid + NTHR*i;
            int pl  = idx / (BROWS*8);
            int rem = idx % (BROWS*8);
            int r   = rem >> 3;
            int q   = rem & 7;
            int rowg = DUAL ? (r < BROWS/2 ? bn + r : bn + 256 + (r - BROWS/2)) : (bn + r);
            const __nv_bfloat16* src = pl ? Bl : Bh;
            cp16(smb + (uint32_t)((so + (pl ? O_BL : O_BH) + r*PITCH + q*8)*2),
                 src + (size_t)rowg*KDIM + cc*64 + q*8);
        }
    };

    // prologue
    if (AF16) cpA16(0, 0); else loadA(0);
    cpB(0, 0);
    CP_COMMIT();
    if (!AF16) {
        storeA(0, 0);
        if (NCHK > 1) loadA(1);
    }

    #pragma unroll 1
    for (int c = 0; c < NCHK; c++) {
        const int so = (c & 1)*STAGE;
        CP_WAIT0();
        __syncthreads();
        if (c + 1 < NCHK) {
            const int nso = ((c+1) & 1)*STAGE;
            cpB(c+1, nso);
            if (AF16) cpA16(c+1, nso);
            CP_COMMIT();
            if (!AF16) {
                storeA(c+1, nso);
                if (c + 2 < NCHK) loadA(c+2);
            }
        }

        #pragma unroll
        for (int kk = 0; kk < 4; kk++) {
            const int kkE = kk*16;
            uint32_t ah[2][4], al[2][4];
            #pragma unroll
            for (int rb = 0; rb < 2; rb++) {
                int abase = so + (32*wr + 16*rb)*PITCH + kkE + aLaneE;
                LDSM4(ah[rb], smb + (uint32_t)((O_AH + abase)*2));
                if (!AF16) LDSM4(al[rb], smb + (uint32_t)((O_AL + abase)*2));
            }
            if (!DUAL) {
                #pragma unroll
                for (int nb2 = 0; nb2 < NBT/2; nb2++) {
                    uint32_t bh[4], bl[4];
                    int bbase = so + (8*NBT*wc4 + 16*nb2)*PITCH + kkE + bLaneE;
                    LDSM4(bh, smb + (uint32_t)((O_BH + bbase)*2));
                    LDSM4(bl, smb + (uint32_t)((O_BL + bbase)*2));
                    #pragma unroll
                    for (int rb = 0; rb < 2; rb++)
                        #pragma unroll
                        for (int j = 0; j < 2; j++) {
                            float* d = accg[rb][2*nb2 + j];
                            if (AF16) {
                                MMA_F16(d, ah[rb], bh[2*j], bh[2*j+1]);
                                MMA_F16(d, ah[rb], bl[2*j], bl[2*j+1]);
                            } else {
                                MMA_BF16(d, ah[rb], bh[2*j], bh[2*j+1]);
                                MMA_BF16(d, al[rb], bh[2*j], bh[2*j+1]);
                                MMA_BF16(d, ah[rb], bl[2*j], bl[2*j+1]);
                            }
                        }
                }
            } else {
                #pragma unroll
                for (int nb2 = 0; nb2 < NBT/2; nb2++) {
                    uint32_t bh[4], bl[4], dh[4], el[4];
                    int bbase = so + (8*NBT*wc4 + 16*nb2)*PITCH + kkE + bLaneE;
                    int sbase = bbase + (32*NBT)*PITCH;
                    LDSM4(bh, smb + (uint32_t)((O_BH + bbase)*2));
                    LDSM4(bl, smb + (uint32_t)((O_BL + bbase)*2));
                    LDSM4(dh, smb + (uint32_t)((O_BH + sbase)*2));
                    LDSM4(el, smb + (uint32_t)((O_BL + sbase)*2));
                    #pragma unroll
                    for (int rb = 0; rb < 2; rb++)
                        #pragma unroll
                        for (int j = 0; j < 2; j++) {
                            float* dg = accg[rb][2*nb2 + j];
                            float* ds = accs[rb][2*nb2 + j];
                            if (AF16) {
                                MMA_F16(dg, ah[rb], bh[2*j], bh[2*j+1]);
                                MMA_F16(dg, ah[rb], bl[2*j], bl[2*j+1]);
                                MMA_F16(ds, ah[rb], dh[2*j], dh[2*j+1]);
                                MMA_F16(ds, ah[rb], el[2*j], el[2*j+1]);
                            } else {
                                MMA_BF16(dg, ah[rb], bh[2*j], bh[2*j+1]);
                                MMA_BF16(dg, al[rb], bh[2*j], bh[2*j+1]);
                                MMA_BF16(dg, ah[rb], bl[2*j], bl[2*j+1]);
                                MMA_BF16(ds, ah[rb], dh[2*j], dh[2*j+1]);
                                MMA_BF16(ds, al[rb], dh[2*j], dh[2*j+1]);
                                MMA_BF16(ds, ah[rb], el[2*j], el[2*j+1]);
                            }
                        }
                }
            }
        }
    }

    // ---- epilogue ----
    float cs0[STATS ? NBT : 1], cs1[STATS ? NBT : 1], cq0[STATS ? NBT : 1], cq1[STATS ? NBT : 1];
    if (STATS) {
        #pragma unroll
        for (int nb = 0; nb < NBT; nb++) { cs0[nb]=0.f; cs1[nb]=0.f; cq0[nb]=0.f; cq1[nb]=0.f; }
    }
    #pragma unroll
    for (int rb = 0; rb < 2; rb++) {
        int m0 = bm + 32*wr + 16*rb + g;
        #pragma unroll
        for (int nb = 0; nb < NBT; nb++) {
            if (!DUAL) {
                int col = bn + 8*NBT*wc4 + 8*nb + 2*t;
                float2 v0 = make_float2(accg[rb][nb][0], accg[rb][nb][1]);
                float2 v1 = make_float2(accg[rb][nb][2], accg[rb][nb][3]);
                if (EPI == 0) {
                    if (bias != nullptr) {
                        float2 bv = *(const float2*)(bias + col);
                        v0.x += bv.x; v0.y += bv.y; v1.x += bv.x; v1.y += bv.y;
                    }
                } else if (EPI == 1) {
                    float2 aa = *(const float2*)(g_bna + col);
                    float2 ab = *(const float2*)(g_bnb + col);
                    float2 dv = *(const float2*)(dvec + col);
                    float2 h0, h1;
                    if (AUXH) {
                        const __half* ah2 = (const __half*)auxv;
                        h0 = __half22float2(*(const __half2*)(ah2 + (size_t)m0*DE + col));
                        h1 = __half22float2(*(const __half2*)(ah2 + (size_t)(m0+8)*DE + col));
                    } else {
                        const float* af = (const float*)auxv;
                        h0 = *(const float2*)(af + (size_t)m0*DE + col);
                        h1 = *(const float2*)(af + (size_t)(m0+8)*DE + col);
                    }
                    v0.x += fmaf(aa.x, h0.x, ab.x)*dv.x;
                    v0.y += fmaf(aa.y, h0.y, ab.y)*dv.y;
                    v1.x += fmaf(aa.x, h1.x, ab.x)*dv.x;
                    v1.y += fmaf(aa.y, h1.y, ab.y)*dv.y;
                } else if (EPI == 2) {
                    float2 bv = *(const float2*)(bias + col);
                    const float* af = (const float*)auxv;
                    float2 y0 = *(const float2*)(af + (size_t)m0*OUTW + col);
                    float2 y1 = *(const float2*)(af + (size_t)(m0+8)*OUTW + col);
                    v0.x += bv.x + y0.x; v0.y += bv.y + y0.y;
                    v1.x += bv.x + y1.x; v1.y += bv.y + y1.y;
                }
                if (STATS) {
                    cs0[nb] += v0.x + v1.x;
                    cs1[nb] += v0.y + v1.y;
                    cq0[nb] += v0.x*v0.x + v1.x*v1.x;
                    cq1[nb] += v0.y*v0.y + v1.y*v1.y;
                }
                if (OUTH == 1) {
                    __half* Ch = (__half*)Cv;
                    *(__half2*)(Ch + (size_t)m0*OUTW + col)     = __floats2half2_rn(v0.x, v0.y);
                    *(__half2*)(Ch + (size_t)(m0+8)*OUTW + col) = __floats2half2_rn(v1.x, v1.y);
                } else if (OUTH == 2) {
                    float* Cf = (float*)Cv;
                    *(float2*)(Cf + (size_t)m0*OUTW + col)     = v0;
                    *(float2*)(Cf + (size_t)(m0+8)*OUTW + col) = v1;
                    *(__half2*)(g_h + (size_t)m0*OUTW + col)     = __floats2half2_rn(v0.x, v0.y);
                    *(__half2*)(g_h + (size_t)(m0+8)*OUTW + col) = __floats2half2_rn(v1.x, v1.y);
                } else {
                    float* Cf = (float*)Cv;
                    *(float2*)(Cf + (size_t)m0*OUTW + col)     = v0;
                    *(float2*)(Cf + (size_t)(m0+8)*OUTW + col) = v1;
                }
            } else {
                int jc = bn + 8*NBT*wc4 + 8*nb + 2*t;
                float2 bg = *(const float2*)(bias + jc);
                float2 bs = *(const float2*)(bias + 256 + jc);
                float g0 = accg[rb][nb][0] + bg.x, s0 = accs[rb][nb][0] + bs.x;
                float g1 = accg[rb][nb][1] + bg.y, s1 = accs[rb][nb][1] + bs.y;
                float g2 = accg[rb][nb][2] + bg.x, s2 = accs[rb][nb][2] + bs.x;
                float g3 = accg[rb][nb][3] + bg.y, s3 = accs[rb][nb][3] + bs.y;
                float2 v0, v1;
                v0.x = g0 * (1.f/(1.f + expf(-s0)));
                v0.y = g1 * (1.f/(1.f + expf(-s1)));
                v1.x = g2 * (1.f/(1.f + expf(-s2)));
                v1.y = g3 * (1.f/(1.f + expf(-s3)));
                __half* Ch = (__half*)Cv;
                *(__half2*)(Ch + (size_t)m0*OUTW + jc)     = __floats2half2_rn(v0.x, v0.y);
                *(__half2*)(Ch + (size_t)(m0+8)*OUTW + jc) = __floats2half2_rn(v1.x, v1.y);
            }
        }
    }

    if (STATS && !DUAL) {
        #pragma unroll
        for (int nb = 0; nb < NBT; nb++) {
            #pragma unroll
            for (int m = 4; m <= 16; m <<= 1) {
                cs0[nb] += __shfl_xor_sync(0xffffffffu, cs0[nb], m);
                cs1[nb] += __shfl_xor_sync(0xffffffffu, cs1[nb], m);
                cq0[nb] += __shfl_xor_sync(0xffffffffu, cq0[nb], m);
                cq1[nb] += __shfl_xor_sync(0xffffffffu, cq1[nb], m);
            }
        }
        __syncthreads();
        float* spart = (float*)sm;
        if (lane < 4) {
            #pragma unroll
            for (int nb = 0; nb < NBT; nb++) {
                int col = 8*NBT*wc4 + 8*nb + 2*lane;
                spart[wr*128 + col]           = cs0[nb];
                spart[wr*128 + col + 1]       = cs1[nb];
                spart[512 + wr*128 + col]     = cq0[nb];
                spart[512 + wr*128 + col + 1] = cq1[nb];
            }
        }
        __syncthreads();
        if (tid < 128) {
            float s  = spart[tid] + spart[128+tid] + spart[256+tid] + spart[384+tid];
            float s2 = spart[512+tid] + spart[640+tid] + spart[768+tid] + spart[896+tid];
            g_bnpart[blockIdx.y*(2*DE) + tid]      = s;
            g_bnpart[blockIdx.y*(2*DE) + DE + tid] = s2;
        }
    }
}

// ---------------- LRU scan (fp16 Bu in, in-place fp16 state out) ----------------
__device__ __forceinline__ float2 cstep(float2 lam, float2 s, float2 u) {
    float2 t;
    t.x = fmaf(lam.x, s.x, fmaf(-lam.y, s.y, u.x));
    t.y = fmaf(lam.x, s.y, fmaf( lam.y, s.x, u.y));
    return t;
}
__device__ __forceinline__ float2 ldh2(const uint32_t* p, size_t off) {
    uint32_t r = p[off];
    return __half22float2(*(__half2*)&r);
}
__global__ void scanA_kernel(int blk) {
    int g  = blockIdx.x*256 + threadIdx.x;
    int h  = g & 255;
    int bc = g >> 8;
    int b  = bc >> 4;
    int c  = bc & 15;
    float2 lam = g_lam[blk*HH + h];
    float2 s = make_float2(0.f, 0.f);
    const uint32_t* p = (const uint32_t*)g_bu;
    size_t base = (size_t)(b*TT + c*CLEN)*256 + h;
    #pragma unroll 8
    for (int i = 0; i < CLEN; i++)
        s = cstep(lam, s, ldh2(p, base + (size_t)i*256));
    g_carry[bc*HH + h] = s;
}
// scanC with inline prefix: inc = sum_{j<c} lam^{256*(c-1-j)} * carry[j]
__global__ void scanC_kernel(int blk) {
    int g  = blockIdx.x*256 + threadIdx.x;
    int h  = g & 255;
    int bc = g >> 8;
    int b  = bc >> 4;
    int c  = bc & 15;
    float2 lam = g_lam[blk*HH + h];
    float2 lp = lam;
    #pragma unroll
    for (int i = 0; i < 8; i++) {
        float2 tt;
        tt.x = lp.x*lp.x - lp.y*lp.y;
        tt.y = 2.f*lp.x*lp.y;
        lp = tt;
    }
    float2 s = make_float2(0.f, 0.f);
    for (int j = 0; j < c; j++) {
        float2 cr = g_carry[(b*NCH + j)*HH + h];
        s = cstep(lp, s, cr);
    }
    uint32_t* p = (uint32_t*)g_bu;
    size_t base = (size_t)(b*TT + c*CLEN)*256 + h;
    #pragma unroll 8
    for (int i = 0; i < CLEN; i++) {
        size_t off = base + (size_t)i*256;
        s = cstep(lam, s, ldh2(p, off));
        __half2 sv = __floats2half2_rn(s.x, s.y);
        p[off] = *(uint32_t*)&sv;
    }
}

// ---------------- final: mean-pool + head (fp16 h) ----------------
__global__ void final_kernel(const float* __restrict__ Wout,
                             const float* __restrict__ bout,
                             float* __restrict__ out) {
    __shared__ float pooled[DE];
    int b = blockIdx.x;
    int f = threadIdx.x;
    float s = 0.f;
    const __half* p = g_h + (size_t)b*TT*DE + f;
    #pragma unroll 4
    for (int t = 0; t < TT; t++) s += __half2float(p[(size_t)t*DE]);
    pooled[f] = s * (1.f/TT);
    __syncthreads();
    if (f < OD) {
        float acc = bout[f];
        #pragma unroll 4
        for (int d = 0; d < DE; d++) acc = fmaf(pooled[d], Wout[d*OD + f], acc);
        out[b*OD + f] = acc;
    }
}

// ---------------- launch ----------------
#define SMEM_ENC   147456   // f32A, NBT=4
#define SMEM_BU16  184320   // f16A, NBT=8
#define SMEM_F16N4 110592   // f16A, NBT=4 (2 CTA/SM)
#define SMEM_GLU   184320   // f16A, DUAL NBT=4

extern "C" void kernel_launch(void* const* d_in, const int* in_sizes, int n_in,
                              void* d_out, int out_size) {
    const float* x         = (const float*)d_in[0];
    const float* nu_log    = (const float*)d_in[1];
    const float* theta_log = (const float*)d_in[2];
    const float* B_re      = (const float*)d_in[3];
    const float* B_im      = (const float*)d_in[4];
    const float* C_re      = (const float*)d_in[5];
    const float* C_im      = (const float*)d_in[6];
    const float* D_lru     = (const float*)d_in[7];
    const float* W1        = (const float*)d_in[8];
    const float* b1        = (const float*)d_in[9];
    const float* W2        = (const float*)d_in[10];
    const float* b2        = (const float*)d_in[11];
    const float* bn_scale  = (const float*)d_in[12];
    const float* bn_bias   = (const float*)d_in[13];
    const float* W_enc     = (const float*)d_in[14];
    const float* b_enc     = (const float*)d_in[15];
    const float* W_out     = (const float*)d_in[16];
    const float* b_out     = (const float*)d_in[17];
    float* out = (float*)d_out;

    float *yenc, *bubias;
    __half *hh, *bu, *lru, *glu, *wbfh, *wbfl, *wch, *wcl, *w1h, *w1l, *w2h, *w2l;
    __nv_bfloat16 *weh, *wel;
    cudaGetSymbolAddress((void**)&yenc, g_yenc);
    cudaGetSymbolAddress((void**)&hh,   g_h);
    cudaGetSymbolAddress((void**)&bu,   g_bu);
    cudaGetSymbolAddress((void**)&lru,  g_lru);
    cudaGetSymbolAddress((void**)&glu,  g_glu);
    cudaGetSymbolAddress((void**)&wbfh, g_WBfh);
    cudaGetSymbolAddress((void**)&wbfl, g_WBfl);
    cudaGetSymbolAddress((void**)&weh,  g_WEh);
    cudaGetSymbolAddress((void**)&wel,  g_WEl);
    cudaGetSymbolAddress((void**)&wch,  g_WCh);
    cudaGetSymbolAddress((void**)&wcl,  g_WCl);
    cudaGetSymbolAddress((void**)&w1h,  g_W1h);
    cudaGetSymbolAddress((void**)&w1l,  g_W1l);
    cudaGetSymbolAddress((void**)&w2h,  g_W2h);
    cudaGetSymbolAddress((void**)&w2l,  g_W2l);
    cudaGetSymbolAddress((void**)&bubias, g_bubias);

    cudaFuncSetAttribute(gemm_mma<64, 128, 0, 0, 0, 0, 2, 1, 4, 0, 1>,  cudaFuncAttributeMaxDynamicSharedMemorySize, SMEM_ENC);
    cudaFuncSetAttribute(gemm_mma<128, 512, 0, 0, 0, 1, 1, 0, 8, 0, 1>, cudaFuncAttributeMaxDynamicSharedMemorySize, SMEM_BU16);
    cudaFuncSetAttribute(gemm_mma<512, 128, 0, 1, 0, 1, 1, 0, 4, 1, 2>, cudaFuncAttributeMaxDynamicSharedMemorySize, SMEM_F16N4);
    cudaFuncSetAttribute(gemm_mma<128, 256, 0, 0, 1, 1, 1, 0, 4, 0, 1>, cudaFuncAttributeMaxDynamicSharedMemorySize, SMEM_GLU);
    cudaFuncSetAttribute(gemm_mma<256, 128, 0, 2, 0, 1, 1, 1, 4, 0, 2>, cudaFuncAttributeMaxDynamicSharedMemorySize, SMEM_F16N4);

    prep_lam_kernel<<<NBLKS, HH>>>(nu_log, theta_log);
    prep_WE_kernel<<<(DE*TSD + 255)/256, 256>>>(W_enc);
    prep_WBf_kernel<<<(NBLKS*512*DE + 255)/256, 256>>>(B_re, B_im);

    // encoder: yenc(fp32) + h copy(fp16) = x @ W_enc + b_enc  (+ BN partials for block 0)
    gemm_mma<64, 128, 0, 0, 0, 0, 2, 1, 4, 0, 1><<<dim3(1, NR/128), NTHR, SMEM_ENC>>>(
        x, weh, wel, yenc, b_enc, nullptr, nullptr);

    prep_WC_kernel<<<(NBLKS*DE*512 + 255)/256, 256>>>(C_re, C_im);
    prep_W1_kernel<<<(NBLKS*512*DE + 255)/256, 256>>>(W1);
    prep_W2_kernel<<<(NBLKS*DE*256 + 255)/256, 256>>>(W2);

    for (int blk = 0; blk < NBLKS; blk++) {
        bn_stats2_kernel<<<1, 512>>>(bn_scale + blk*DE, bn_bias + blk*DE);
        fold_kernel<<<257, 256>>>(blk);

        // Bu = h @ (diag(a)WB) + (b.WB)   (fp16 A, 2-term, 256-wide tiles)
        gemm_mma<128, 512, 0, 0, 0, 1, 1, 0, 8, 0, 1><<<dim3(2, NR/128), NTHR, SMEM_BU16>>>(
            hh, wbfh, wbfl, bu, bubias, nullptr, nullptr);

        scanA_kernel<<<NR/256, 256>>>(blk);
        scanC_kernel<<<NR/256, 256>>>(blk);

        // lru = Re(state @ C) + BN(h) * D   (2 CTA/SM)
        gemm_mma<512, 128, 0, 1, 0, 1, 1, 0, 4, 1, 2><<<dim3(1, NR/128), NTHR, SMEM_F16N4>>>(
            bu, wch + (size_t)blk*128*512, wcl + (size_t)blk*128*512,
            lru, nullptr, hh, D_lru + blk*DE);

        // glu = GLU(lru @ W1 + b1)
        gemm_mma<128, 256, 0, 0, 1, 1, 1, 0, 4, 0, 1><<<dim3(2, NR/128), NTHR, SMEM_GLU>>>(
            lru, w1h + (size_t)blk*512*128, w1l + (size_t)blk*512*128,
            glu, b1 + (size_t)blk*LDF, nullptr, nullptr);

        // h(fp16) = glu @ W2 + b2 + yenc(fp32)  (+ BN partials; 2 CTA/SM)
        gemm_mma<256, 128, 0, 2, 0, 1, 1, 1, 4, 0, 2><<<dim3(1, NR/128), NTHR, SMEM_F16N4>>>(
            glu, w2h + (size_t)blk*128*256, w2l + (size_t)blk*128*256,
            hh, b2 + blk*DE, yenc, nullptr);
    }

    final_kernel<<<BB, DE>>>(W_out, b_out, out);
}

// round 16
// speedup vs baseline: 1.1133x; 1.0470x over previous
#include <cuda_runtime.h>
#include <cuda_bf16.h>
#include <cuda_fp16.h>
#include <math.h>
#include <stdint.h>

// ---------------- problem constants ----------------
#define BB   16
#define TT   4096
#define NR   (BB*TT)
#define TSD  64
#define DE   128
#define HH   256
#define LDF  512
#define LDH  256
#define OD   10
#define NBLKS 6
#define EPSV 1e-5f
#define NCH  16
#define CLEN 256

// ---------------- scratch ----------------
static __device__ __align__(256) float  g_yenc[(size_t)NR*DE];  // fp32 residual anchor
static __device__ __align__(256) __half g_h  [(size_t)NR*DE];   // running hidden, fp16
static __device__ __align__(256) __half g_lru[(size_t)NR*DE];
static __device__ __align__(256) __half g_glu[(size_t)NR*LDH];
static __device__ __align__(256) __half g_bu [(size_t)NR*512];  // Bu -> state (in place), fp16
static __device__ float2 g_lam [NBLKS*HH];
static __device__ float  g_gamma[NBLKS*HH];
static __device__ float  g_bnpart[512*2*DE];
static __device__ float  g_bna[DE];
static __device__ float  g_bnb[DE];
static __device__ float  g_bubias[512];
static __device__ float2 g_carry[BB*NCH*HH];

// weights
static __device__ __align__(256) float  g_WBf[(size_t)NBLKS*512*128]; // gamma-scaled fp32 master
static __device__ __align__(256) __half g_WBfh[512*128];              // per-block BN-folded, fp16 split
static __device__ __align__(256) __half g_WBfl[512*128];
static __device__ __align__(256) __nv_bfloat16 g_WEh[128*64];
static __device__ __align__(256) __nv_bfloat16 g_WEl[128*64];
static __device__ __align__(256) __half g_WCh[(size_t)NBLKS*128*512];
static __device__ __align__(256) __half g_WCl[(size_t)NBLKS*128*512];
static __device__ __align__(256) __half g_W1h[(size_t)NBLKS*512*128];
static __device__ __align__(256) __half g_W1l[(size_t)NBLKS*512*128];
static __device__ __align__(256) __half g_W2h[(size_t)NBLKS*128*256];
static __device__ __align__(256) __half g_W2l[(size_t)NBLKS*128*256];

// ---------------- helpers ----------------
__device__ __forceinline__ uint32_t smem_u32(const void* p) {
    uint32_t a;
    asm("{ .reg .u64 t; cvta.to.shared.u64 t, %1; cvt.u32.u64 %0, t; }" : "=r"(a) : "l"(p));
    return a;
}
__device__ __forceinline__ void cp16(uint32_t dst, const void* src) {
    asm volatile("cp.async.cg.shared.global [%0], [%1], 16;" :: "r"(dst), "l"(src));
}
#define CP_COMMIT() asm volatile("cp.async.commit_group;" ::: "memory")
#define CP_WAIT0()  asm volatile("cp.async.wait_group 0;" ::: "memory")

#define MMA_BF16(d, a, b0, b1) \
    asm volatile("mma.sync.aligned.m16n8k16.row.col.f32.bf16.bf16.f32 " \
        "{%0,%1,%2,%3}, {%4,%5,%6,%7}, {%8,%9}, {%0,%1,%2,%3};" \
        : "+f"((d)[0]), "+f"((d)[1]), "+f"((d)[2]), "+f"((d)[3]) \
        : "r"((a)[0]), "r"((a)[1]), "r"((a)[2]), "r"((a)[3]), "r"(b0), "r"(b1))

#define MMA_F16(d, a, b0, b1) \
    asm volatile("mma.sync.aligned.m16n8k16.row.col.f32.f16.f16.f32 " \
        "{%0,%1,%2,%3}, {%4,%5,%6,%7}, {%8,%9}, {%0,%1,%2,%3};" \
        : "+f"((d)[0]), "+f"((d)[1]), "+f"((d)[2]), "+f"((d)[3]) \
        : "r"((a)[0]), "r"((a)[1]), "r"((a)[2]), "r"((a)[3]), "r"(b0), "r"(b1))

#define LDSM4(r, addr) \
    asm volatile("ldmatrix.sync.aligned.m8n8.x4.shared.b16 {%0,%1,%2,%3}, [%4];" \
        : "=r"((r)[0]), "=r"((r)[1]), "=r"((r)[2]), "=r"((r)[3]) : "r"(addr))

__device__ __forceinline__ void split_store(float v, __nv_bfloat16* hi, __nv_bfloat16* lo, size_t i) {
    __nv_bfloat16 h = __float2bfloat16(v);
    hi[i] = h;
    lo[i] = __float2bfloat16(v - __bfloat162float(h));
}
__device__ __forceinline__ void split_store_h(float v, __half* hi, __half* lo, size_t i) {
    __half h = __float2half_rn(v);
    hi[i] = h;
    lo[i] = __float2half_rn(v - __half2float(h));
}

// ---------------- prep ----------------
__global__ void prep_lam_kernel(const float* __restrict__ nu_log,
                                const float* __restrict__ theta_log) {
    int blk = blockIdx.x;
    int h   = threadIdx.x;
    float nu = nu_log[blk*HH + h];
    float th = theta_log[blk*HH + h];
    float r  = expf(-expf(nu));
    float ang = expf(th);
    float sn, cs;
    sincosf(ang, &sn, &cs);
    float2 lam; lam.x = r*cs; lam.y = r*sn;
    g_lam[blk*HH + h]   = lam;
    g_gamma[blk*HH + h] = sqrtf(fmaxf(1.f - r*r, 1e-8f));
}
__global__ void prep_WBf_kernel(const float* __restrict__ Bre, const float* __restrict__ Bim) {
    int idx = blockIdx.x*256 + threadIdx.x;
    if (idx >= NBLKS*512*DE) return;
    int k = idx & 127;
    int n = (idx >> 7) & 511;
    int blk = idx >> 16;
    int h = n >> 1;
    float g = g_gamma[blk*HH + h];
    g_WBf[idx] = ((n & 1) ? Bim : Bre)[((size_t)blk*HH + h)*DE + k] * g;
}
__global__ void prep_WC_kernel(const float* __restrict__ Cre, const float* __restrict__ Cim) {
    int idx = blockIdx.x*256 + threadIdx.x;
    if (idx >= NBLKS*DE*512) return;
    int k = idx & 511;
    int n = (idx >> 9) & 127;
    int blk = idx >> 16;
    int h = k >> 1;
    float v = (k & 1) ? -Cim[((size_t)blk*DE + n)*HH + h] : Cre[((size_t)blk*DE + n)*HH + h];
    split_store_h(v, g_WCh, g_WCl, idx);
}
__global__ void prep_W1_kernel(const float* __restrict__ W1) {
    int idx = blockIdx.x*256 + threadIdx.x;
    if (idx >= NBLKS*512*DE) return;
    int k = idx & 127;
    int n = (idx >> 7) & 511;
    int blk = idx >> 16;
    split_store_h(W1[((size_t)blk*DE + k)*LDF + n], g_W1h, g_W1l, idx);
}
__global__ void prep_W2_kernel(const float* __restrict__ W2) {
    int idx = blockIdx.x*256 + threadIdx.x;
    if (idx >= NBLKS*DE*256) return;
    int k = idx & 255;
    int n = (idx >> 8) & 127;
    int blk = idx >> 15;
    split_store_h(W2[((size_t)blk*LDH + k)*DE + n], g_W2h, g_W2l, idx);
}
__global__ void prep_WE_kernel(const float* __restrict__ We) {
    int idx = blockIdx.x*256 + threadIdx.x;
    if (idx >= DE*TSD) return;
    int k = idx & 63;
    int n = idx >> 6;
    split_store(We[(size_t)k*DE + n], g_WEh, g_WEl, idx);
}

// ---------------- batchnorm stage-2 + merged BN fold ----------------
__global__ void bn_stats2_kernel(const float* __restrict__ scale,
                                 const float* __restrict__ bias) {
    __shared__ float ss[512], sq[512];
    int tid = threadIdx.x;
    int f = tid & 127;
    int grp = tid >> 7;
    float s = 0.f, s2 = 0.f;
    for (int i = grp; i < 512; i += 4) {
        s  += g_bnpart[i*(2*DE) + f];
        s2 += g_bnpart[i*(2*DE) + DE + f];
    }
    ss[tid] = s;
    sq[tid] = s2;
    __syncthreads();
    if (tid < 128) {
        s  = ss[tid] + ss[128+tid] + ss[256+tid] + ss[384+tid];
        s2 = sq[tid] + sq[128+tid] + sq[256+tid] + sq[384+tid];
        float mean = s * (1.f/NR);
        float var  = s2 * (1.f/NR) - mean*mean;
        float a = scale[tid] * rsqrtf(var + EPSV);
        g_bna[tid] = a;
        g_bnb[tid] = fmaf(-mean, a, bias[tid]);
    }
}
// blocks 0..255: scale+split WB; block 256: fold bias (2 n per thread)
__global__ void fold_kernel(int blk) {
    if (blockIdx.x < 256) {
        int idx = blockIdx.x*256 + threadIdx.x;
        int k = idx & 127;
        float v = g_WBf[(size_t)blk*512*128 + idx] * g_bna[k];
        split_store_h(v, g_WBfh, g_WBfl, idx);
    } else {
        #pragma unroll
        for (int r = 0; r < 2; r++) {
            int n = threadIdx.x + 256*r;
            const float* w = g_WBf + (size_t)blk*512*128 + (size_t)n*128;
            float s = 0.f;
            #pragma unroll 4
            for (int k = 0; k < 128; k++) s = fmaf(g_bnb[k], w[k], s);
            g_bubias[n] = s;
        }
    }
}

// ---------------- GEMM: 512 threads, 16 warps (4x4), variable N tile ----------------
// AF16=0: A fp32 reg-staged -> bf16 split (3-term). AF16=1: A fp16, 2-term fp16 MMA.
// EPI: 0 +bias?; 1 cproj (+(a*aux+b)*d, aux fp16 if AUXH); 2 +bias+aux residual (fp32).
// OUTH: 0 fp32 out; 1 fp16 out; 2 fp32 out + fp16 copy into g_h.
// STATS: per-CTA BN partials (grid.x==1, NBT==4, !DUAL). NBT: n8-tiles per warp.
// MINB: min blocks/SM (2 for all 110KB-smem kernels -> co-resident CTAs).
#define PITCH 72
#define UNITE (128*PITCH)
#define NTHR 512

template<int KDIM, int OUTW, int MODE_A, int EPI, int DUAL, int AF16, int OUTH, int STATS, int NBT, int AUXH, int MINB>
__global__ void __launch_bounds__(NTHR, MINB) gemm_mma(
    const void* __restrict__ Av,
    const void* __restrict__ Bhi_, const void* __restrict__ Blo_,
    void* __restrict__ Cv,
    const float* __restrict__ bias,
    const void* __restrict__ auxv,
    const float* __restrict__ dvec)
{
    constexpr int ABUFS = AF16 ? 1 : 2;
    constexpr int BROWS = (DUAL ? 64 : 32) * NBT;
    constexpr int BUNIT = BROWS * PITCH;
    constexpr int O_AH = 0, O_AL = UNITE;
    constexpr int O_BH = ABUFS*UNITE;
    constexpr int O_BL = O_BH + BUNIT;
    constexpr int STAGE = ABUFS*UNITE + 2*BUNIT;
    constexpr int NCHK = KDIM / 64;
    constexpr int CPB_IT = (BROWS*16)/NTHR;

    extern __shared__ __nv_bfloat16 sm[];
    const uint32_t smb = smem_u32(sm);
    const int tid  = threadIdx.x;
    const int lane = tid & 31;
    const int wid  = tid >> 5;
    const int wr   = wid & 3;
    const int wc4  = wid >> 2;
    const int g    = lane >> 2;
    const int t    = lane & 3;
    const int bm   = blockIdx.y << 7;
    const int bn   = blockIdx.x * (32*NBT);

    const int aLaneE = (lane & 15)*PITCH + (lane >> 4)*8;
    const int bLaneE = (lane & 7)*PITCH + ((lane >> 4) & 1)*(8*PITCH) + ((lane >> 3) & 1)*8;

    float accg[2][NBT][4];
    float accs[DUAL ? 2 : 1][DUAL ? NBT : 1][4];
    #pragma unroll
    for (int rb = 0; rb < 2; rb++)
        #pragma unroll
        for (int nb = 0; nb < NBT; nb++)
            #pragma unroll
            for (int j = 0; j < 4; j++) {
                accg[rb][nb][j] = 0.f;
                if (DUAL) accs[rb][nb][j] = 0.f;
            }

    float4 areg[4];
    auto loadA = [&](int cc) {
        const float* Af = (const float*)Av;
        #pragma unroll
        for (int i = 0; i < 4; i++) {
            int idx = tid + NTHR*i;
            int row = idx >> 4;
            int col4 = (idx & 15) << 2;
            areg[i] = *(const float4*)(Af + (size_t)(bm + row)*KDIM + cc*64 + col4);
        }
    };
    auto storeA = [&](int cc, int so) {
        #pragma unroll
        for (int i = 0; i < 4; i++) {
            int idx = tid + NTHR*i;
            int row = idx >> 4;
            int col4 = (idx & 15) << 2;
            float4 v = areg[i];
            if (MODE_A) {
                float4 aa = *(const float4*)(g_bna + cc*64 + col4);
                float4 ab = *(const float4*)(g_bnb + cc*64 + col4);
                v.x = fmaf(aa.x, v.x, ab.x);
                v.y = fmaf(aa.y, v.y, ab.y);
                v.z = fmaf(aa.z, v.z, ab.z);
                v.w = fmaf(aa.w, v.w, ab.w);
            }
            __nv_bfloat16 h0 = __float2bfloat16(v.x), h1 = __float2bfloat16(v.y);
            __nv_bfloat16 h2 = __float2bfloat16(v.z), h3 = __float2bfloat16(v.w);
            __nv_bfloat16 l0 = __float2bfloat16(v.x - __bfloat162float(h0));
            __nv_bfloat16 l1 = __float2bfloat16(v.y - __bfloat162float(h1));
            __nv_bfloat16 l2 = __float2bfloat16(v.z - __bfloat162float(h2));
            __nv_bfloat16 l3 = __float2bfloat16(v.w - __bfloat162float(h3));
            uint32_t hu0 = ((uint32_t)__bfloat16_as_ushort(h1) << 16) | __bfloat16_as_ushort(h0);
            uint32_t hu1 = ((uint32_t)__bfloat16_as_ushort(h3) << 16) | __bfloat16_as_ushort(h2);
            uint32_t lu0 = ((uint32_t)__bfloat16_as_ushort(l1) << 16) | __bfloat16_as_ushort(l0);
            uint32_t lu1 = ((uint32_t)__bfloat16_as_ushort(l3) << 16) | __bfloat16_as_ushort(l2);
            int off = row*PITCH + col4;
            *(uint2*)(sm + so + O_AH + off) = make_uint2(hu0, hu1);
            *(uint2*)(sm + so + O_AL + off) = make_uint2(lu0, lu1);
        }
    };
    auto cpA16 = [&](int cc, int so) {
        const __half* Ahalf = (const __half*)Av;
        #pragma unroll
        for (int i = 0; i < 2; i++) {
            int idx = tid + NTHR*i;
            int r = idx >> 3;
            int q = idx & 7;
            cp16(smb + (uint32_t)((so + O_AH + r*PITCH + q*8)*2),
                 Ahalf + (size_t)(bm + r)*KDIM + cc*64 + q*8);
        }
    };
    auto cpB = [&](int cc, int so) {
        const __nv_bfloat16* Bh = (const __nv_bfloat16*)Bhi_;
        const __nv_bfloat16* Bl = (const __nv_bfloat16*)Blo_;
        #pragma unroll
        for (int i = 0; i < CPB_IT; i++) {
            int idx = tid + NTHR*i;
            int pl  = idx / (BROWS*8);
            int rem = idx % (BROWS*8);
            int r   = rem >> 3;
            int q   = rem & 7;
            int rowg = DUAL ? (r < BROWS/2 ? bn + r : bn + 256 + (r - BROWS/2)) : (bn + r);
            const __nv_bfloat16* src = pl ? Bl : Bh;
            cp16(smb + (uint32_t)((so + (pl ? O_BL : O_BH) + r*PITCH + q*8)*2),
                 src + (size_t)rowg*KDIM + cc*64 + q*8);
        }
    };

    // prologue
    if (AF16) cpA16(0, 0); else loadA(0);
    cpB(0, 0);
    CP_COMMIT();
    if (!AF16) {
        storeA(0, 0);
        if (NCHK > 1) loadA(1);
    }

    #pragma unroll 1
    for (int c = 0; c < NCHK; c++) {
        const int so = (c & 1)*STAGE;
        CP_WAIT0();
        __syncthreads();
        if (c + 1 < NCHK) {
            const int nso = ((c+1) & 1)*STAGE;
            cpB(c+1, nso);
            if (AF16) cpA16(c+1, nso);
            CP_COMMIT();
            if (!AF16) {
                storeA(c+1, nso);
                if (c + 2 < NCHK) loadA(c+2);
            }
        }

        #pragma unroll
        for (int kk = 0; kk < 4; kk++) {
            const int kkE = kk*16;
            uint32_t ah[2][4], al[2][4];
            #pragma unroll
            for (int rb = 0; rb < 2; rb++) {
                int abase = so + (32*wr + 16*rb)*PITCH + kkE + aLaneE;
                LDSM4(ah[rb], smb + (uint32_t)((O_AH + abase)*2));
                if (!AF16) LDSM4(al[rb], smb + (uint32_t)((O_AL + abase)*2));
            }
            if (!DUAL) {
                #pragma unroll
                for (int nb2 = 0; nb2 < NBT/2; nb2++) {
                    uint32_t bh[4], bl[4];
                    int bbase = so + (8*NBT*wc4 + 16*nb2)*PITCH + kkE + bLaneE;
                    LDSM4(bh, smb + (uint32_t)((O_BH + bbase)*2));
                    LDSM4(bl, smb + (uint32_t)((O_BL + bbase)*2));
                    #pragma unroll
                    for (int rb = 0; rb < 2; rb++)
                        #pragma unroll
                        for (int j = 0; j < 2; j++) {
                            float* d = accg[rb][2*nb2 + j];
                            if (AF16) {
                                MMA_F16(d, ah[rb], bh[2*j], bh[2*j+1]);
                                MMA_F16(d, ah[rb], bl[2*j], bl[2*j+1]);
                            } else {
                                MMA_BF16(d, ah[rb], bh[2*j], bh[2*j+1]);
                                MMA_BF16(d, al[rb], bh[2*j], bh[2*j+1]);
                                MMA_BF16(d, ah[rb], bl[2*j], bl[2*j+1]);
                            }
                        }
                }
            } else {
                #pragma unroll
                for (int nb2 = 0; nb2 < NBT/2; nb2++) {
                    uint32_t bh[4], bl[4], dh[4], el[4];
                    int bbase = so + (8*NBT*wc4 + 16*nb2)*PITCH + kkE + bLaneE;
                    int sbase = bbase + (32*NBT)*PITCH;
                    LDSM4(bh, smb + (uint32_t)((O_BH + bbase)*2));
                    LDSM4(bl, smb + (uint32_t)((O_BL + bbase)*2));
                    LDSM4(dh, smb + (uint32_t)((O_BH + sbase)*2));
                    LDSM4(el, smb + (uint32_t)((O_BL + sbase)*2));
                    #pragma unroll
                    for (int rb = 0; rb < 2; rb++)
                        #pragma unroll
                        for (int j = 0; j < 2; j++) {
                            float* dg = accg[rb][2*nb2 + j];
                            float* ds = accs[rb][2*nb2 + j];
                            if (AF16) {
                                MMA_F16(dg, ah[rb], bh[2*j], bh[2*j+1]);
                                MMA_F16(dg, ah[rb], bl[2*j], bl[2*j+1]);
                                MMA_F16(ds, ah[rb], dh[2*j], dh[2*j+1]);
                                MMA_F16(ds, ah[rb], el[2*j], el[2*j+1]);
                            } else {
                                MMA_BF16(dg, ah[rb], bh[2*j], bh[2*j+1]);
                                MMA_BF16(dg, al[rb], bh[2*j], bh[2*j+1]);
                                MMA_BF16(dg, ah[rb], bl[2*j], bl[2*j+1]);
                                MMA_BF16(ds, ah[rb], dh[2*j], dh[2*j+1]);
                                MMA_BF16(ds, al[rb], dh[2*j], dh[2*j+1]);
                                MMA_BF16(ds, ah[rb], el[2*j], el[2*j+1]);
                            }
                        }
                }
            }
        }
    }

    // ---- epilogue ----
    float cs0[STATS ? NBT : 1], cs1[STATS ? NBT : 1], cq0[STATS ? NBT : 1], cq1[STATS ? NBT : 1];
    if (STATS) {
        #pragma unroll
        for (int nb = 0; nb < NBT; nb++) { cs0[nb]=0.f; cs1[nb]=0.f; cq0[nb]=0.f; cq1[nb]=0.f; }
    }
    #pragma unroll
    for (int rb = 0; rb < 2; rb++) {
        int m0 = bm + 32*wr + 16*rb + g;
        #pragma unroll
        for (int nb = 0; nb < NBT; nb++) {
            if (!DUAL) {
                int col = bn + 8*NBT*wc4 + 8*nb + 2*t;
                float2 v0 = make_float2(accg[rb][nb][0], accg[rb][nb][1]);
                float2 v1 = make_float2(accg[rb][nb][2], accg[rb][nb][3]);
                if (EPI == 0) {
                    if (bias != nullptr) {
                        float2 bv = *(const float2*)(bias + col);
                        v0.x += bv.x; v0.y += bv.y; v1.x += bv.x; v1.y += bv.y;
                    }
                } else if (EPI == 1) {
                    float2 aa = *(const float2*)(g_bna + col);
                    float2 ab = *(const float2*)(g_bnb + col);
                    float2 dv = *(const float2*)(dvec + col);
                    float2 h0, h1;
                    if (AUXH) {
                        const __half* ah2 = (const __half*)auxv;
                        h0 = __half22float2(*(const __half2*)(ah2 + (size_t)m0*DE + col));
                        h1 = __half22float2(*(const __half2*)(ah2 + (size_t)(m0+8)*DE + col));
                    } else {
                        const float* af = (const float*)auxv;
                        h0 = *(const float2*)(af + (size_t)m0*DE + col);
                        h1 = *(const float2*)(af + (size_t)(m0+8)*DE + col);
                    }
                    v0.x += fmaf(aa.x, h0.x, ab.x)*dv.x;
                    v0.y += fmaf(aa.y, h0.y, ab.y)*dv.y;
                    v1.x += fmaf(aa.x, h1.x, ab.x)*dv.x;
                    v1.y += fmaf(aa.y, h1.y, ab.y)*dv.y;
                } else if (EPI == 2) {
                    float2 bv = *(const float2*)(bias + col);
                    const float* af = (const float*)auxv;
                    float2 y0 = *(const float2*)(af + (size_t)m0*OUTW + col);
                    float2 y1 = *(const float2*)(af + (size_t)(m0+8)*OUTW + col);
                    v0.x += bv.x + y0.x; v0.y += bv.y + y0.y;
                    v1.x += bv.x + y1.x; v1.y += bv.y + y1.y;
                }
                if (STATS) {
                    cs0[nb] += v0.x + v1.x;
                    cs1[nb] += v0.y + v1.y;
                    cq0[nb] += v0.x*v0.x + v1.x*v1.x;
                    cq1[nb] += v0.y*v0.y + v1.y*v1.y;
                }
                if (OUTH == 1) {
                    __half* Ch = (__half*)Cv;
                    *(__half2*)(Ch + (size_t)m0*OUTW + col)     = __floats2half2_rn(v0.x, v0.y);
                    *(__half2*)(Ch + (size_t)(m0+8)*OUTW + col) = __floats2half2_rn(v1.x, v1.y);
                } else if (OUTH == 2) {
                    float* Cf = (float*)Cv;
                    *(float2*)(Cf + (size_t)m0*OUTW + col)     = v0;
                    *(float2*)(Cf + (size_t)(m0+8)*OUTW + col) = v1;
                    *(__half2*)(g_h + (size_t)m0*OUTW + col)     = __floats2half2_rn(v0.x, v0.y);
                    *(__half2*)(g_h + (size_t)(m0+8)*OUTW + col) = __floats2half2_rn(v1.x, v1.y);
                } else {
                    float* Cf = (float*)Cv;
                    *(float2*)(Cf + (size_t)m0*OUTW + col)     = v0;
                    *(float2*)(Cf + (size_t)(m0+8)*OUTW + col) = v1;
                }
            } else {
                int jc = bn + 8*NBT*wc4 + 8*nb + 2*t;
                float2 bg = *(const float2*)(bias + jc);
                float2 bs = *(const float2*)(bias + 256 + jc);
                float g0 = accg[rb][nb][0] + bg.x, s0 = accs[rb][nb][0] + bs.x;
                float g1 = accg[rb][nb][1] + bg.y, s1 = accs[rb][nb][1] + bs.y;
                float g2 = accg[rb][nb][2] + bg.x, s2 = accs[rb][nb][2] + bs.x;
                float g3 = accg[rb][nb][3] + bg.y, s3 = accs[rb][nb][3] + bs.y;
                float2 v0, v1;
                v0.x = g0 * (1.f/(1.f + expf(-s0)));
                v0.y = g1 * (1.f/(1.f + expf(-s1)));
                v1.x = g2 * (1.f/(1.f + expf(-s2)));
                v1.y = g3 * (1.f/(1.f + expf(-s3)));
                __half* Ch = (__half*)Cv;
                *(__half2*)(Ch + (size_t)m0*OUTW + jc)     = __floats2half2_rn(v0.x, v0.y);
                *(__half2*)(Ch + (size_t)(m0+8)*OUTW + jc) = __floats2half2_rn(v1.x, v1.y);
            }
        }
    }

    if (STATS && !DUAL) {
        #pragma unroll
        for (int nb = 0; nb < NBT; nb++) {
            #pragma unroll
            for (int m = 4; m <= 16; m <<= 1) {
                cs0[nb] += __shfl_xor_sync(0xffffffffu, cs0[nb], m);
                cs1[nb] += __shfl_xor_sync(0xffffffffu, cs1[nb], m);
                cq0[nb] += __shfl_xor_sync(0xffffffffu, cq0[nb], m);
                cq1[nb] += __shfl_xor_sync(0xffffffffu, cq1[nb], m);
            }
        }
        __syncthreads();
        float* spart = (float*)sm;
        if (lane < 4) {
            #pragma unroll
            for (int nb = 0; nb < NBT; nb++) {
                int col = 8*NBT*wc4 + 8*nb + 2*lane;
                spart[wr*128 + col]           = cs0[nb];
                spart[wr*128 + col + 1]       = cs1[nb];
                spart[512 + wr*128 + col]     = cq0[nb];
                spart[512 + wr*128 + col + 1] = cq1[nb];
            }
        }
        __syncthreads();
        if (tid < 128) {
            float s  = spart[tid] + spart[128+tid] + spart[256+tid] + spart[384+tid];
            float s2 = spart[512+tid] + spart[640+tid] + spart[768+tid] + spart[896+tid];
            g_bnpart[blockIdx.y*(2*DE) + tid]      = s;
            g_bnpart[blockIdx.y*(2*DE) + DE + tid] = s2;
        }
    }
}

// ---------------- LRU scan (fp16 Bu in, in-place fp16 state out) ----------------
__device__ __forceinline__ float2 cstep(float2 lam, float2 s, float2 u) {
    float2 t;
    t.x = fmaf(lam.x, s.x, fmaf(-lam.y, s.y, u.x));
    t.y = fmaf(lam.x, s.y, fmaf( lam.y, s.x, u.y));
    return t;
}
__device__ __forceinline__ float2 ldh2(const uint32_t* p, size_t off) {
    uint32_t r = p[off];
    return __half22float2(*(__half2*)&r);
}
__global__ void scanA_kernel(int blk) {
    int g  = blockIdx.x*256 + threadIdx.x;
    int h  = g & 255;
    int bc = g >> 8;
    int b  = bc >> 4;
    int c  = bc & 15;
    float2 lam = g_lam[blk*HH + h];
    float2 s = make_float2(0.f, 0.f);
    const uint32_t* p = (const uint32_t*)g_bu;
    size_t base = (size_t)(b*TT + c*CLEN)*256 + h;
    #pragma unroll 8
    for (int i = 0; i < CLEN; i++)
        s = cstep(lam, s, ldh2(p, base + (size_t)i*256));
    g_carry[bc*HH + h] = s;
}
// scanC with inline prefix: inc = sum_{j<c} lam^{256*(c-1-j)} * carry[j]
__global__ void scanC_kernel(int blk) {
    int g  = blockIdx.x*256 + threadIdx.x;
    int h  = g & 255;
    int bc = g >> 8;
    int b  = bc >> 4;
    int c  = bc & 15;
    float2 lam = g_lam[blk*HH + h];
    float2 lp = lam;
    #pragma unroll
    for (int i = 0; i < 8; i++) {
        float2 tt;
        tt.x = lp.x*lp.x - lp.y*lp.y;
        tt.y = 2.f*lp.x*lp.y;
        lp = tt;
    }
    float2 s = make_float2(0.f, 0.f);
    for (int j = 0; j < c; j++) {
        float2 cr = g_carry[(b*NCH + j)*HH + h];
        s = cstep(lp, s, cr);
    }
    uint32_t* p = (uint32_t*)g_bu;
    size_t base = (size_t)(b*TT + c*CLEN)*256 + h;
    #pragma unroll 8
    for (int i = 0; i < CLEN; i++) {
        size_t off = base + (size_t)i*256;
        s = cstep(lam, s, ldh2(p, off));
        __half2 sv = __floats2half2_rn(s.x, s.y);
        p[off] = *(uint32_t*)&sv;
    }
}

// ---------------- final: mean-pool + head (fp16 h) ----------------
__global__ void final_kernel(const float* __restrict__ Wout,
                             const float* __restrict__ bout,
                             float* __restrict__ out) {
    __shared__ float pooled[DE];
    int b = blockIdx.x;
    int f = threadIdx.x;
    float s = 0.f;
    const __half* p = g_h + (size_t)b*TT*DE + f;
    #pragma unroll 4
    for (int t = 0; t < TT; t++) s += __half2float(p[(size_t)t*DE]);
    pooled[f] = s * (1.f/TT);
    __syncthreads();
    if (f < OD) {
        float acc = bout[f];
        #pragma unroll 4
        for (int d = 0; d < DE; d++) acc = fmaf(pooled[d], Wout[d*OD + f], acc);
        out[b*OD + f] = acc;
    }
}

// ---------------- launch ----------------
#define SMEM_ENC   147456   // f32A, NBT=4
#define SMEM_F16N4 110592   // f16A: Bu NBT=4, cproj NBT=4, GLU DUAL NBT=2, W2 NBT=4 (all 2 CTA/SM)

extern "C" void kernel_launch(void* const* d_in, const int* in_sizes, int n_in,
                              void* d_out, int out_size) {
    const float* x         = (const float*)d_in[0];
    const float* nu_log    = (const float*)d_in[1];
    const float* theta_log = (const float*)d_in[2];
    const float* B_re      = (const float*)d_in[3];
    const float* B_im      = (const float*)d_in[4];
    const float* C_re      = (const float*)d_in[5];
    const float* C_im      = (const float*)d_in[6];
    const float* D_lru     = (const float*)d_in[7];
    const float* W1        = (const float*)d_in[8];
    const float* b1        = (const float*)d_in[9];
    const float* W2        = (const float*)d_in[10];
    const float* b2        = (const float*)d_in[11];
    const float* bn_scale  = (const float*)d_in[12];
    const float* bn_bias   = (const float*)d_in[13];
    const float* W_enc     = (const float*)d_in[14];
    const float* b_enc     = (const float*)d_in[15];
    const float* W_out     = (const float*)d_in[16];
    const float* b_out     = (const float*)d_in[17];
    float* out = (float*)d_out;

    float *yenc, *bubias;
    __half *hh, *bu, *lru, *glu, *wbfh, *wbfl, *wch, *wcl, *w1h, *w1l, *w2h, *w2l;
    __nv_bfloat16 *weh, *wel;
    cudaGetSymbolAddress((void**)&yenc, g_yenc);
    cudaGetSymbolAddress((void**)&hh,   g_h);
    cudaGetSymbolAddress((void**)&bu,   g_bu);
    cudaGetSymbolAddress((void**)&lru,  g_lru);
    cudaGetSymbolAddress((void**)&glu,  g_glu);
    cudaGetSymbolAddress((void**)&wbfh, g_WBfh);
    cudaGetSymbolAddress((void**)&wbfl, g_WBfl);
    cudaGetSymbolAddress((void**)&weh,  g_WEh);
    cudaGetSymbolAddress((void**)&wel,  g_WEl);
    cudaGetSymbolAddress((void**)&wch,  g_WCh);
    cudaGetSymbolAddress((void**)&wcl,  g_WCl);
    cudaGetSymbolAddress((void**)&w1h,  g_W1h);
    cudaGetSymbolAddress((void**)&w1l,  g_W1l);
    cudaGetSymbolAddress((void**)&w2h,  g_W2h);
    cudaGetSymbolAddress((void**)&w2l,  g_W2l);
    cudaGetSymbolAddress((void**)&bubias, g_bubias);

    cudaFuncSetAttribute(gemm_mma<64, 128, 0, 0, 0, 0, 2, 1, 4, 0, 1>,  cudaFuncAttributeMaxDynamicSharedMemorySize, SMEM_ENC);
    cudaFuncSetAttribute(gemm_mma<128, 512, 0, 0, 0, 1, 1, 0, 4, 0, 2>, cudaFuncAttributeMaxDynamicSharedMemorySize, SMEM_F16N4);
    cudaFuncSetAttribute(gemm_mma<512, 128, 0, 1, 0, 1, 1, 0, 4, 1, 2>, cudaFuncAttributeMaxDynamicSharedMemorySize, SMEM_F16N4);
    cudaFuncSetAttribute(gemm_mma<128, 256, 0, 0, 1, 1, 1, 0, 2, 0, 2>, cudaFuncAttributeMaxDynamicSharedMemorySize, SMEM_F16N4);
    cudaFuncSetAttribute(gemm_mma<256, 128, 0, 2, 0, 1, 1, 1, 4, 0, 2>, cudaFuncAttributeMaxDynamicSharedMemorySize, SMEM_F16N4);

    prep_lam_kernel<<<NBLKS, HH>>>(nu_log, theta_log);
    prep_WE_kernel<<<(DE*TSD + 255)/256, 256>>>(W_enc);
    prep_WBf_kernel<<<(NBLKS*512*DE + 255)/256, 256>>>(B_re, B_im);

    // encoder: yenc(fp32) + h copy(fp16) = x @ W_enc + b_enc  (+ BN partials for block 0)
    gemm_mma<64, 128, 0, 0, 0, 0, 2, 1, 4, 0, 1><<<dim3(1, NR/128), NTHR, SMEM_ENC>>>(
        x, weh, wel, yenc, b_enc, nullptr, nullptr);

    prep_WC_kernel<<<(NBLKS*DE*512 + 255)/256, 256>>>(C_re, C_im);
    prep_W1_kernel<<<(NBLKS*512*DE + 255)/256, 256>>>(W1);
    prep_W2_kernel<<<(NBLKS*DE*256 + 255)/256, 256>>>(W2);

    for (int blk = 0; blk < NBLKS; blk++) {
        bn_stats2_kernel<<<1, 512>>>(bn_scale + blk*DE, bn_bias + blk*DE);
        fold_kernel<<<257, 256>>>(blk);

        // Bu = h @ (diag(a)WB) + (b.WB)   (fp16 A, 2-term, 128-wide tiles, 2 CTA/SM)
        gemm_mma<128, 512, 0, 0, 0, 1, 1, 0, 4, 0, 2><<<dim3(4, NR/128), NTHR, SMEM_F16N4>>>(
            hh, wbfh, wbfl, bu, bubias, nullptr, nullptr);

        scanA_kernel<<<NR/256, 256>>>(blk);
        scanC_kernel<<<NR/256, 256>>>(blk);

        // lru = Re(state @ C) + BN(h) * D   (2 CTA/SM)
        gemm_mma<512, 128, 0, 1, 0, 1, 1, 0, 4, 1, 2><<<dim3(1, NR/128), NTHR, SMEM_F16N4>>>(
            bu, wch + (size_t)blk*128*512, wcl + (size_t)blk*128*512,
            lru, nullptr, hh, D_lru + blk*DE);

        // glu = GLU(lru @ W1 + b1)   (64 gate cols per CTA, 2 CTA/SM)
        gemm_mma<128, 256, 0, 0, 1, 1, 1, 0, 2, 0, 2><<<dim3(4, NR/128), NTHR, SMEM_F16N4>>>(
            lru, w1h + (size_t)blk*512*128, w1l + (size_t)blk*512*128,
            glu, b1 + (size_t)blk*LDF, nullptr, nullptr);

        // h(fp16) = glu @ W2 + b2 + yenc(fp32)  (+ BN partials; 2 CTA/SM)
        gemm_mma<256, 128, 0, 2, 0, 1, 1, 1, 4, 0, 2><<<dim3(1, NR/128), NTHR, SMEM_F16N4>>>(
            glu, w2h + (size_t)blk*128*256, w2l + (size_t)blk*128*256,
            hh, b2 + blk*DE, yenc, nullptr);
    }

    final_kernel<<<BB, DE>>>(W_out, b_out, out);
}